// round 2
// baseline (speedup 1.0000x reference)
#include <cuda_runtime.h>
#include <cstdint>

#define N_NODES 50000
#define E_EDGES 800000
#define S_SAMP  4
#define D_OUT   128
#define ADJ_STRIDE 128        // padded adjacency slots per node (max degree ~45)
#define MAIN_BLOCKS 6250      // N_NODES / 8

// ---------------- scratch (static device globals; no allocs) ----------------
__device__ unsigned int g_eps_pack[S_SAMP * N_NODES];   // [n][s] packed bits
__device__ int   g_cnt[N_NODES];                        // in-degree / slot counter
__device__ int   g_adj[(size_t)N_NODES * ADJ_STRIDE];   // padded in-neighbor lists
__device__ float g_q[(size_t)N_NODES * 128];            // projected shared features
__device__ float g_part[(size_t)MAIN_BLOCKS * S_SAMP * 128];
__device__ float g_part2[64 * S_SAMP * 128];
__device__ float g_means[S_SAMP * 128];

// ---------------- f32x2 packed math helpers ----------------
__device__ __forceinline__ unsigned long long f2pack(float lo, float hi) {
    unsigned long long r;
    asm("mov.b64 %0, {%1, %2};" : "=l"(r) : "f"(lo), "f"(hi));
    return r;
}
__device__ __forceinline__ void f2fma(unsigned long long& d, unsigned long long a, unsigned long long b) {
    asm("fma.rn.f32x2 %0, %1, %2, %0;" : "+l"(d) : "l"(a), "l"(b));
}
__device__ __forceinline__ void f2unpack(float& lo, float& hi, unsigned long long v) {
    asm("mov.b64 {%0, %1}, %2;" : "=f"(lo), "=f"(hi) : "l"(v));
}

// ---------------- setup kernels ----------------
__global__ void zero_cnt_kernel() {
    int i = blockIdx.x * blockDim.x + threadIdx.x;
    if (i < N_NODES) g_cnt[i] = 0;
}

// one warp per (s,n): pack 32 Bernoulli floats into a bitmask
__global__ void pack_kernel(const float* __restrict__ eps) {
    int g = blockIdx.x * 8 + (threadIdx.x >> 5);
    int lane = threadIdx.x & 31;
    if (g >= S_SAMP * N_NODES) return;
    int s = g / N_NODES;
    int n = g - s * N_NODES;
    float v = eps[(size_t)g * 32 + lane];
    unsigned m = __ballot_sync(0xffffffffu, v > 0.5f);
    if (lane == 0) g_eps_pack[n * 4 + s] = m;
}

// padded-adjacency fill: counting + placement in one pass, no scan needed
__global__ void fill_kernel(const int* __restrict__ src, const int* __restrict__ dst) {
    int e = blockIdx.x * blockDim.x + threadIdx.x;
    if (e < E_EDGES) {
        int d = dst[e];
        int slot = atomicAdd(&g_cnt[d], 1);
        if (slot < ADJ_STRIDE)
            g_adj[(size_t)d * ADJ_STRIDE + slot] = src[e];
    }
}

// ---------------- q = [X,h] @ W_shared  (N x 128) ----------------
// block: 256 threads = (32 lanes x 8), 32 nodes per block
__global__ void __launch_bounds__(256) q_kernel(const float* __restrict__ X,
                                                const float* __restrict__ H,
                                                const float* __restrict__ W) {
    __shared__ float  xs[32][128];     // 16 KB
    __shared__ float4 Ws[32][32];      // 16 KB
    int tid = threadIdx.x, lane = tid & 31, wy = tid >> 5;
    int node0 = blockIdx.x * 32;

    for (int idx = tid; idx < 32 * 128; idx += 256) {
        int nn = idx >> 7, k = idx & 127;
        int n = node0 + nn;
        float v = 0.f;
        if (n < N_NODES) v = (k < 96) ? X[(size_t)n * 96 + k] : H[(size_t)n * 32 + (k - 96)];
        xs[nn][k] = v;
    }

    unsigned long long accA[4], accB[4];
    #pragma unroll
    for (int j = 0; j < 4; j++) { accA[j] = f2pack(0.f, 0.f); accB[j] = f2pack(0.f, 0.f); }

    for (int kc = 0; kc < 4; kc++) {
        __syncthreads();
        for (int idx = tid; idx < 32 * 128; idx += 256) {
            int kk = idx >> 7, c = idx & 127;
            int k = kc * 32 + kk;
            int wrow = (k < 96) ? k : (k + 32);   // skip epsilon rows 96..127 of W
            ((float*)Ws)[idx] = W[wrow * 128 + c];
        }
        __syncthreads();
        #pragma unroll
        for (int kk = 0; kk < 32; kk++) {
            float4 w4 = Ws[kk][lane];
            unsigned long long wA = f2pack(w4.x, w4.y), wB = f2pack(w4.z, w4.w);
            #pragma unroll
            for (int j = 0; j < 4; j++) {
                float xv = xs[wy + j * 8][kc * 32 + kk];
                unsigned long long xp = f2pack(xv, xv);
                f2fma(accA[j], xp, wA);
                f2fma(accB[j], xp, wB);
            }
        }
    }
    #pragma unroll
    for (int j = 0; j < 4; j++) {
        int n = node0 + wy + j * 8;
        if (n < N_NODES) {
            float4 r;
            f2unpack(r.x, r.y, accA[j]);
            f2unpack(r.z, r.w, accB[j]);
            *(float4*)&g_q[(size_t)n * 128 + 4 * lane] = r;
        }
    }
}

// ---------------- main: neighbor-sum + eps-GEMV + relu + block mean ----------------
// block: 256 threads = 8 warps = 8 nodes
__global__ void __launch_bounds__(256) main_kernel(const float* __restrict__ bias,
                                                   const float* __restrict__ W,
                                                   const float* __restrict__ gin_eps) {
    __shared__ float4 Weps[32][32];    // 16 KB: W rows 96..127 (epsilon block)
    __shared__ float  bsm[128];
    __shared__ float  zs[8 * 4 * 128]; // 16 KB
    int tid = threadIdx.x, lane = tid & 31, wid = tid >> 5;

    for (int idx = tid; idx < 32 * 128; idx += 256) {
        int f = idx >> 7, c = idx & 127;
        ((float*)Weps)[idx] = W[(96 + f) * 128 + c];
    }
    if (tid < 128) bsm[tid] = bias[tid];
    __syncthreads();

    int n = blockIdx.x * 8 + wid;       // exact: 6250*8 == N_NODES
    float c0 = 1.f + *gin_eps;

    float4 acc = *(const float4*)&g_q[(size_t)n * 128 + 4 * lane];
    acc.x *= c0; acc.y *= c0; acc.z *= c0; acc.w *= c0;

    uint4 selfp = *(const uint4*)&g_eps_pack[n * 4];
    int cnt0 = 0, cnt1 = 0, cnt2 = 0, cnt3 = 0;

    int deg = g_cnt[n];
    if (deg > ADJ_STRIDE) deg = ADJ_STRIDE;
    const int* adj = &g_adj[(size_t)n * ADJ_STRIDE];
    #pragma unroll 2
    for (int e = 0; e < deg; e++) {
        int j = adj[e];
        float4 qv = *(const float4*)&g_q[(size_t)j * 128 + 4 * lane];
        acc.x += qv.x; acc.y += qv.y; acc.z += qv.z; acc.w += qv.w;
        uint4 p = *(const uint4*)&g_eps_pack[j * 4];
        cnt0 += (p.x >> lane) & 1;
        cnt1 += (p.y >> lane) & 1;
        cnt2 += (p.z >> lane) & 1;
        cnt3 += (p.w >> lane) & 1;
    }

    float coeff[4];
    coeff[0] = (float)cnt0 + c0 * (float)((selfp.x >> lane) & 1);
    coeff[1] = (float)cnt1 + c0 * (float)((selfp.y >> lane) & 1);
    coeff[2] = (float)cnt2 + c0 * (float)((selfp.z >> lane) & 1);
    coeff[3] = (float)cnt3 + c0 * (float)((selfp.w >> lane) & 1);

    float4 b4 = ((const float4*)bsm)[lane];
    unsigned long long zA[4], zB[4];
    #pragma unroll
    for (int s = 0; s < 4; s++) {
        zA[s] = f2pack(acc.x + b4.x, acc.y + b4.y);
        zB[s] = f2pack(acc.z + b4.z, acc.w + b4.w);
    }
    #pragma unroll
    for (int f = 0; f < 32; f++) {
        float4 w4 = Weps[f][lane];
        unsigned long long wA = f2pack(w4.x, w4.y), wB = f2pack(w4.z, w4.w);
        #pragma unroll
        for (int s = 0; s < 4; s++) {
            float cf = __shfl_sync(0xffffffffu, coeff[s], f);
            unsigned long long cf2 = f2pack(cf, cf);
            f2fma(zA[s], cf2, wA);
            f2fma(zB[s], cf2, wB);
        }
    }
    #pragma unroll
    for (int s = 0; s < 4; s++) {
        float4 r;
        f2unpack(r.x, r.y, zA[s]);
        f2unpack(r.z, r.w, zB[s]);
        r.x = fmaxf(r.x, 0.f); r.y = fmaxf(r.y, 0.f);
        r.z = fmaxf(r.z, 0.f); r.w = fmaxf(r.w, 0.f);
        ((float4*)zs)[(wid * 4 + s) * 32 + lane] = r;
    }
    __syncthreads();

    for (int p = tid; p < 512; p += 256) {
        float v = 0.f;
        #pragma unroll
        for (int w = 0; w < 8; w++) v += zs[w * 512 + p];
        g_part[(size_t)blockIdx.x * 512 + p] = v;
    }
}

// ---------------- two-stage deterministic mean reduction ----------------
__global__ void reduce1_kernel() {
    int tid = threadIdx.x;            // 512
    int b = blockIdx.x;               // 64
    float v = 0.f;
    for (int i = b; i < MAIN_BLOCKS; i += 64) v += g_part[(size_t)i * 512 + tid];
    g_part2[b * 512 + tid] = v;
}
__global__ void reduce2_kernel() {
    int tid = threadIdx.x;            // 512
    float v = 0.f;
    #pragma unroll
    for (int i = 0; i < 64; i++) v += g_part2[i * 512 + tid];
    g_means[tid] = fmaxf(v * (1.f / (float)N_NODES), 0.f);  // mean + outer relu
}

// ---------------- broadcast means + epsilon tail -> output ----------------
// out layout: [S,N,128] means-broadcast, then [S,N,32] epsilon (if out_size allows)
__global__ void bcast_kernel(float4* __restrict__ out,
                             const float4* __restrict__ eps,
                             long long out_size_f4) {
    const int MAIN_F4 = S_SAMP * N_NODES * 32;     // 6.4M float4
    const int EPS_F4  = S_SAMP * N_NODES * 8;      // 1.6M float4
    int idx = blockIdx.x * blockDim.x + threadIdx.x;
    if (idx < MAIN_F4) {
        if ((long long)idx < out_size_f4) {
            int s = idx / (N_NODES * 32);
            int c4 = idx & 31;
            out[idx] = ((const float4*)g_means)[s * 32 + c4];
        }
    } else {
        int k = idx - MAIN_F4;
        if (k < EPS_F4 && (long long)idx < out_size_f4) {
            out[idx] = eps[k];
        }
    }
}

// ---------------- launch ----------------
extern "C" void kernel_launch(void* const* d_in, const int* in_sizes, int n_in,
                              void* d_out, int out_size) {
    const float* X    = (const float*)d_in[0];
    const float* H    = (const float*)d_in[1];
    const float* eps  = (const float*)d_in[2];
    const float* W    = (const float*)d_in[3];
    const float* bias = (const float*)d_in[4];
    const float* geps = (const float*)d_in[5];
    const int*   src  = (const int*)d_in[6];
    const int*   dst  = (const int*)d_in[7];

    zero_cnt_kernel<<<(N_NODES + 255) / 256, 256>>>();
    pack_kernel<<<(S_SAMP * N_NODES + 7) / 8, 256>>>(eps);
    fill_kernel<<<(E_EDGES + 255) / 256, 256>>>(src, dst);
    q_kernel<<<(N_NODES + 31) / 32, 256>>>(X, H, W);
    main_kernel<<<MAIN_BLOCKS, 256>>>(bias, W, geps);
    reduce1_kernel<<<64, 512>>>();
    reduce2_kernel<<<1, 512>>>();

    int total_f4 = S_SAMP * N_NODES * 32 + S_SAMP * N_NODES * 8;
    bcast_kernel<<<(total_f4 + 255) / 256, 256>>>((float4*)d_out,
                                                  (const float4*)eps,
                                                  (long long)out_size / 4);
}

// round 3
// speedup vs baseline: 1.3042x; 1.3042x over previous
#include <cuda_runtime.h>
#include <cstdint>

#define N_NODES 50000
#define E_EDGES 800000
#define S_SAMP  4
#define D_OUT   128
#define ADJ_STRIDE 128        // padded adjacency slots per node (max degree ~45)
#define MAIN_BLOCKS 6250      // N_NODES / 8
#define Q_NODES_PER_BLOCK 64
#define Q_BLOCKS ((N_NODES + Q_NODES_PER_BLOCK - 1) / Q_NODES_PER_BLOCK)

// ---------------- scratch (static device globals; no allocs) ----------------
__device__ unsigned int g_eps_pack[S_SAMP * N_NODES];   // [n][s] packed bits
__device__ int   g_cnt[N_NODES];                        // in-degree / slot counter
__device__ int   g_adj[(size_t)N_NODES * ADJ_STRIDE];   // padded in-neighbor lists
__device__ float g_q[(size_t)N_NODES * 128];            // projected shared features
__device__ float g_part[(size_t)MAIN_BLOCKS * S_SAMP * 128];
__device__ float g_part2[64 * S_SAMP * 128];
__device__ float g_means[S_SAMP * 128];

// ---------------- f32x2 packed math helpers ----------------
__device__ __forceinline__ unsigned long long f2pack(float lo, float hi) {
    unsigned long long r;
    asm("mov.b64 %0, {%1, %2};" : "=l"(r) : "f"(lo), "f"(hi));
    return r;
}
__device__ __forceinline__ void f2fma(unsigned long long& d, unsigned long long a, unsigned long long b) {
    asm("fma.rn.f32x2 %0, %1, %2, %0;" : "+l"(d) : "l"(a), "l"(b));
}
__device__ __forceinline__ void f2unpack(float& lo, float& hi, unsigned long long v) {
    asm("mov.b64 {%0, %1}, %2;" : "=f"(lo), "=f"(hi) : "l"(v));
}

// ---------------- setup kernels ----------------
__global__ void zero_cnt_kernel() {
    int i = blockIdx.x * blockDim.x + threadIdx.x;
    if (i < N_NODES) g_cnt[i] = 0;
}

// one warp per (s,n): pack 32 Bernoulli floats into a bitmask
__global__ void pack_kernel(const float* __restrict__ eps) {
    int g = blockIdx.x * 8 + (threadIdx.x >> 5);
    int lane = threadIdx.x & 31;
    if (g >= S_SAMP * N_NODES) return;
    int s = g / N_NODES;
    int n = g - s * N_NODES;
    float v = eps[(size_t)g * 32 + lane];
    unsigned m = __ballot_sync(0xffffffffu, v > 0.5f);
    if (lane == 0) g_eps_pack[n * 4 + s] = m;
}

// padded-adjacency fill: counting + placement in one pass, no scan needed
__global__ void fill_kernel(const int* __restrict__ src, const int* __restrict__ dst) {
    int e = blockIdx.x * blockDim.x + threadIdx.x;
    if (e < E_EDGES) {
        int d = dst[e];
        int slot = atomicAdd(&g_cnt[d], 1);
        if (slot < ADJ_STRIDE)
            g_adj[(size_t)d * ADJ_STRIDE + slot] = src[e];
    }
}

// ---------------- q = [X,h] @ W_shared  (N x 128) ----------------
// block: 256 threads = 8 warps; 8 nodes per warp -> 64 nodes per block.
// Each W LDS.128 feeds 16 FFMA2 (vs 8 before): shifts from crossbar- to fma-bound.
__global__ void __launch_bounds__(256) q_kernel(const float* __restrict__ X,
                                                const float* __restrict__ H,
                                                const float* __restrict__ W) {
    __shared__ float  xs[Q_NODES_PER_BLOCK][128];   // 32 KB
    __shared__ float4 Ws[32][32];                   // 16 KB (32 W rows x 128 cols)
    int tid = threadIdx.x, lane = tid & 31, wy = tid >> 5;
    int node0 = blockIdx.x * Q_NODES_PER_BLOCK;

    for (int idx = tid; idx < Q_NODES_PER_BLOCK * 128; idx += 256) {
        int nn = idx >> 7, k = idx & 127;
        int n = node0 + nn;
        float v = 0.f;
        if (n < N_NODES) v = (k < 96) ? X[(size_t)n * 96 + k] : H[(size_t)n * 32 + (k - 96)];
        xs[nn][k] = v;
    }

    unsigned long long accA[8], accB[8];
    #pragma unroll
    for (int j = 0; j < 8; j++) { accA[j] = f2pack(0.f, 0.f); accB[j] = f2pack(0.f, 0.f); }

    const float* xrow = &xs[wy * 8][0];   // this warp's 8 nodes are contiguous rows

    for (int kc = 0; kc < 4; kc++) {
        __syncthreads();
        for (int idx = tid; idx < 32 * 128; idx += 256) {
            int kk = idx >> 7, c = idx & 127;
            int k = kc * 32 + kk;
            int wrow = (k < 96) ? k : (k + 32);   // skip epsilon rows 96..127 of W
            ((float*)Ws)[idx] = W[wrow * 128 + c];
        }
        __syncthreads();
        #pragma unroll
        for (int kk = 0; kk < 32; kk++) {
            float4 w4 = Ws[kk][lane];
            unsigned long long wA = f2pack(w4.x, w4.y), wB = f2pack(w4.z, w4.w);
            int kcol = kc * 32 + kk;
            #pragma unroll
            for (int j = 0; j < 8; j++) {
                float xv = xrow[j * 128 + kcol];   // broadcast LDS
                unsigned long long xp = f2pack(xv, xv);
                f2fma(accA[j], xp, wA);
                f2fma(accB[j], xp, wB);
            }
        }
    }
    #pragma unroll
    for (int j = 0; j < 8; j++) {
        int n = node0 + wy * 8 + j;
        if (n < N_NODES) {
            float4 r;
            f2unpack(r.x, r.y, accA[j]);
            f2unpack(r.z, r.w, accB[j]);
            *(float4*)&g_q[(size_t)n * 128 + 4 * lane] = r;
        }
    }
}

// ---------------- main: neighbor-sum + eps-GEMV + relu + block mean ----------------
// block: 256 threads = 8 warps = 8 nodes
__global__ void __launch_bounds__(256) main_kernel(const float* __restrict__ bias,
                                                   const float* __restrict__ W,
                                                   const float* __restrict__ gin_eps) {
    __shared__ float4 Weps[32][32];    // 16 KB: W rows 96..127 (epsilon block)
    __shared__ float  bsm[128];
    __shared__ float  zs[8 * 4 * 128]; // 16 KB
    int tid = threadIdx.x, lane = tid & 31, wid = tid >> 5;

    for (int idx = tid; idx < 32 * 128; idx += 256) {
        int f = idx >> 7, c = idx & 127;
        ((float*)Weps)[idx] = W[(96 + f) * 128 + c];
    }
    if (tid < 128) bsm[tid] = bias[tid];
    __syncthreads();

    int n = blockIdx.x * 8 + wid;       // exact: 6250*8 == N_NODES
    float c0 = 1.f + *gin_eps;

    float4 acc = *(const float4*)&g_q[(size_t)n * 128 + 4 * lane];
    acc.x *= c0; acc.y *= c0; acc.z *= c0; acc.w *= c0;

    uint4 selfp = *(const uint4*)&g_eps_pack[n * 4];
    int cnt0 = 0, cnt1 = 0, cnt2 = 0, cnt3 = 0;

    int deg = g_cnt[n];
    if (deg > ADJ_STRIDE) deg = ADJ_STRIDE;
    const int* adj = &g_adj[(size_t)n * ADJ_STRIDE];
    #pragma unroll 4
    for (int e = 0; e < deg; e++) {
        int j = adj[e];
        float4 qv = *(const float4*)&g_q[(size_t)j * 128 + 4 * lane];
        acc.x += qv.x; acc.y += qv.y; acc.z += qv.z; acc.w += qv.w;
        uint4 p = *(const uint4*)&g_eps_pack[j * 4];
        cnt0 += (p.x >> lane) & 1;
        cnt1 += (p.y >> lane) & 1;
        cnt2 += (p.z >> lane) & 1;
        cnt3 += (p.w >> lane) & 1;
    }

    float coeff[4];
    coeff[0] = (float)cnt0 + c0 * (float)((selfp.x >> lane) & 1);
    coeff[1] = (float)cnt1 + c0 * (float)((selfp.y >> lane) & 1);
    coeff[2] = (float)cnt2 + c0 * (float)((selfp.z >> lane) & 1);
    coeff[3] = (float)cnt3 + c0 * (float)((selfp.w >> lane) & 1);

    float4 b4 = ((const float4*)bsm)[lane];
    unsigned long long zA[4], zB[4];
    #pragma unroll
    for (int s = 0; s < 4; s++) {
        zA[s] = f2pack(acc.x + b4.x, acc.y + b4.y);
        zB[s] = f2pack(acc.z + b4.z, acc.w + b4.w);
    }
    #pragma unroll
    for (int f = 0; f < 32; f++) {
        float4 w4 = Weps[f][lane];
        unsigned long long wA = f2pack(w4.x, w4.y), wB = f2pack(w4.z, w4.w);
        #pragma unroll
        for (int s = 0; s < 4; s++) {
            float cf = __shfl_sync(0xffffffffu, coeff[s], f);
            unsigned long long cf2 = f2pack(cf, cf);
            f2fma(zA[s], cf2, wA);
            f2fma(zB[s], cf2, wB);
        }
    }
    #pragma unroll
    for (int s = 0; s < 4; s++) {
        float4 r;
        f2unpack(r.x, r.y, zA[s]);
        f2unpack(r.z, r.w, zB[s]);
        r.x = fmaxf(r.x, 0.f); r.y = fmaxf(r.y, 0.f);
        r.z = fmaxf(r.z, 0.f); r.w = fmaxf(r.w, 0.f);
        ((float4*)zs)[(wid * 4 + s) * 32 + lane] = r;
    }
    __syncthreads();

    for (int p = tid; p < 512; p += 256) {
        float v = 0.f;
        #pragma unroll
        for (int w = 0; w < 8; w++) v += zs[w * 512 + p];
        g_part[(size_t)blockIdx.x * 512 + p] = v;
    }
}

// ---------------- two-stage deterministic mean reduction ----------------
__global__ void reduce1_kernel() {
    int tid = threadIdx.x;            // 512
    int b = blockIdx.x;               // 64
    float v = 0.f;
    for (int i = b; i < MAIN_BLOCKS; i += 64) v += g_part[(size_t)i * 512 + tid];
    g_part2[b * 512 + tid] = v;
}
__global__ void reduce2_kernel() {
    int tid = threadIdx.x;            // 512
    float v = 0.f;
    #pragma unroll
    for (int i = 0; i < 64; i++) v += g_part2[i * 512 + tid];
    g_means[tid] = fmaxf(v * (1.f / (float)N_NODES), 0.f);  // mean + outer relu
}

// ---------------- broadcast means + epsilon tail -> output ----------------
__global__ void bcast_kernel(float4* __restrict__ out,
                             const float4* __restrict__ eps,
                             long long out_size_f4) {
    const int MAIN_F4 = S_SAMP * N_NODES * 32;     // 6.4M float4
    const int EPS_F4  = S_SAMP * N_NODES * 8;      // 1.6M float4
    int idx = blockIdx.x * blockDim.x + threadIdx.x;
    if (idx < MAIN_F4) {
        if ((long long)idx < out_size_f4) {
            int s = idx / (N_NODES * 32);
            int c4 = idx & 31;
            out[idx] = ((const float4*)g_means)[s * 32 + c4];
        }
    } else {
        int k = idx - MAIN_F4;
        if (k < EPS_F4 && (long long)idx < out_size_f4) {
            out[idx] = eps[k];
        }
    }
}

// ---------------- launch ----------------
extern "C" void kernel_launch(void* const* d_in, const int* in_sizes, int n_in,
                              void* d_out, int out_size) {
    const float* X    = (const float*)d_in[0];
    const float* H    = (const float*)d_in[1];
    const float* eps  = (const float*)d_in[2];
    const float* W    = (const float*)d_in[3];
    const float* bias = (const float*)d_in[4];
    const float* geps = (const float*)d_in[5];
    const int*   src  = (const int*)d_in[6];
    const int*   dst  = (const int*)d_in[7];

    zero_cnt_kernel<<<(N_NODES + 255) / 256, 256>>>();
    pack_kernel<<<(S_SAMP * N_NODES + 7) / 8, 256>>>(eps);
    fill_kernel<<<(E_EDGES + 255) / 256, 256>>>(src, dst);
    q_kernel<<<Q_BLOCKS, 256>>>(X, H, W);
    main_kernel<<<MAIN_BLOCKS, 256>>>(bias, W, geps);
    reduce1_kernel<<<64, 512>>>();
    reduce2_kernel<<<1, 512>>>();

    int total_f4 = S_SAMP * N_NODES * 32 + S_SAMP * N_NODES * 8;
    bcast_kernel<<<(total_f4 + 255) / 256, 256>>>((float4*)d_out,
                                                  (const float4*)eps,
                                                  (long long)out_size / 4);
}

// round 10
// speedup vs baseline: 1.6909x; 1.2965x over previous
#include <cuda_runtime.h>
#include <cuda_bf16.h>
#include <cstdint>

#define N_NODES 50000
#define E_EDGES 800000
#define S_SAMP  4
#define ADJ_STRIDE 128
#define MAIN_BLOCKS 6250      // N_NODES / 8
#define QT_TILE 128
#define QT_BLOCKS ((N_NODES + QT_TILE - 1) / QT_TILE)   // 391
#define BSTRIDE 72            // bf16 elements per B smem row (144B; conflict-free frag loads)

// ---------------- scratch (static device globals; no allocs) ----------------
__device__ unsigned int g_eps_pack[S_SAMP * N_NODES];
__device__ int   g_cnt[N_NODES];
__device__ int   g_adj[(size_t)N_NODES * ADJ_STRIDE];
__device__ float g_q[(size_t)N_NODES * 128];
__device__ float g_part[(size_t)MAIN_BLOCKS * S_SAMP * 128];
__device__ float g_part2[64 * S_SAMP * 128];
__device__ float g_means[S_SAMP * 128];

// ---------------- f32x2 packed math helpers ----------------
__device__ __forceinline__ unsigned long long f2pack(float lo, float hi) {
    unsigned long long r;
    asm("mov.b64 %0, {%1, %2};" : "=l"(r) : "f"(lo), "f"(hi));
    return r;
}
__device__ __forceinline__ void f2fma(unsigned long long& d, unsigned long long a, unsigned long long b) {
    asm("fma.rn.f32x2 %0, %1, %2, %0;" : "+l"(d) : "l"(a), "l"(b));
}
__device__ __forceinline__ void f2unpack(float& lo, float& hi, unsigned long long v) {
    asm("mov.b64 {%0, %1}, %2;" : "=f"(lo), "=f"(hi) : "l"(v));
}

// split fp32 pair -> (hi bf16x2, lo bf16x2)
__device__ __forceinline__ void cvt_split(float2 v, uint32_t& hi, uint32_t& lo) {
    __nv_bfloat162 h2 = __floats2bfloat162_rn(v.x, v.y);
    float fx = __bfloat162float(h2.x), fy = __bfloat162float(h2.y);
    __nv_bfloat162 l2 = __floats2bfloat162_rn(v.x - fx, v.y - fy);
    hi = *(uint32_t*)&h2;
    lo = *(uint32_t*)&l2;
}

__device__ __forceinline__ void mma16816(float* c, const uint32_t* a, uint32_t b0, uint32_t b1) {
    asm volatile("mma.sync.aligned.m16n8k16.row.col.f32.bf16.bf16.f32 "
                 "{%0,%1,%2,%3}, {%4,%5,%6,%7}, {%8,%9}, {%0,%1,%2,%3};"
                 : "+f"(c[0]), "+f"(c[1]), "+f"(c[2]), "+f"(c[3])
                 : "r"(a[0]), "r"(a[1]), "r"(a[2]), "r"(a[3]), "r"(b0), "r"(b1));
}

// ---------------- setup kernels ----------------
__global__ void zero_cnt_kernel() {
    int i = blockIdx.x * blockDim.x + threadIdx.x;
    if (i < N_NODES) g_cnt[i] = 0;
}

__global__ void pack_kernel(const float* __restrict__ eps) {
    int g = blockIdx.x * 8 + (threadIdx.x >> 5);
    int lane = threadIdx.x & 31;
    if (g >= S_SAMP * N_NODES) return;
    int s = g / N_NODES;
    int n = g - s * N_NODES;
    float v = eps[(size_t)g * 32 + lane];
    unsigned m = __ballot_sync(0xffffffffu, v > 0.5f);
    if (lane == 0) g_eps_pack[n * 4 + s] = m;
}

__global__ void fill_kernel(const int* __restrict__ src, const int* __restrict__ dst) {
    int e = blockIdx.x * blockDim.x + threadIdx.x;
    if (e < E_EDGES) {
        int d = dst[e];
        int slot = atomicAdd(&g_cnt[d], 1);
        if (slot < ADJ_STRIDE)
            g_adj[(size_t)d * ADJ_STRIDE + slot] = src[e];
    }
}

// ---------------- q = [X,h] @ W_shared via mma.sync split-bf16 ----------------
// 128 nodes/CTA, 8 warps x 16 rows x ALL 128 cols (16 n-tiles of m16n8 per warp).
// A frags from global in regs; B = W^T staged [n][k] in smem (two 64-wide k-halves).
// B fragments via direct LDS.32 per the mma.m16n8k16 spec:
//   b0 = {B[2(t%4)][t/4], B[2(t%4)+1][t/4]}, b1 = same at k+8.
__global__ void __launch_bounds__(256) q_mma_kernel(const float* __restrict__ X,
                                                    const float* __restrict__ H,
                                                    const float* __restrict__ W) {
    __shared__ __nv_bfloat16 Bhi[128 * BSTRIDE];   // 18432 B
    __shared__ __nv_bfloat16 Blo[128 * BSTRIDE];   // 18432 B

    int tid = threadIdx.x, lane = tid & 31, wid = tid >> 5;
    int tg = lane & 3;
    int node0 = blockIdx.x * QT_TILE;
    int m0 = node0 + wid * 16 + (lane >> 2);   // row for c0/c1; m0+8 for c2/c3
    bool v0 = m0 < N_NODES, v1 = (m0 + 8) < N_NODES;

    const float* rowX0 = X + (size_t)m0 * 96;
    const float* rowH0 = H + (size_t)m0 * 32;
    const float* rowX1 = rowX0 + 8 * 96;
    const float* rowH1 = rowH0 + 8 * 32;

    float C[16][4];    // 16 n-tiles of 8 cols -> full 128 output columns
    #pragma unroll
    for (int t = 0; t < 16; t++)
        #pragma unroll
        for (int i = 0; i < 4; i++) C[t][i] = 0.f;

    int bn = lane >> 2;        // n-within-8 for B fragments
    int bk = (lane & 3) * 2;   // k-pair base for B fragments

    for (int half = 0; half < 2; half++) {
        __syncthreads();
        // stage B[n][k] = W[wrow(k)][n] for k in [half*64, half*64+64), split hi/lo
        for (int idx = tid; idx < 32 * 128; idx += 256) {
            int kp = idx >> 7, n = idx & 127;
            int k = half * 64 + kp * 2;
            int wr0 = (k < 96) ? k : (k + 32);          // skip eps rows 96..127 of W
            int wr1 = (k + 1 < 96) ? (k + 1) : (k + 33);
            float2 v = make_float2(W[wr0 * 128 + n], W[wr1 * 128 + n]);
            uint32_t hi, lo;
            cvt_split(v, hi, lo);
            *(uint32_t*)&Bhi[n * BSTRIDE + kp * 2] = hi;
            *(uint32_t*)&Blo[n * BSTRIDE + kp * 2] = lo;
        }
        __syncthreads();

        #pragma unroll
        for (int ks = 0; ks < 4; ks++) {
            int k0 = half * 64 + ks * 16;
            // ---- A fragments from global (split hi/lo), per mma spec ----
            uint32_t a_hi[4], a_lo[4];
            int kA = k0 + tg * 2;
            int kB = kA + 8;
            float2 z = make_float2(0.f, 0.f);
            float2 p0, p1, p2, p3;
            if (k0 < 96) {   // whole 16-wide k-slab inside X (k0 mult of 16; 96 = 6*16)
                p0 = v0 ? *(const float2*)(rowX0 + kA) : z;
                p1 = v1 ? *(const float2*)(rowX1 + kA) : z;
                p2 = v0 ? *(const float2*)(rowX0 + kB) : z;
                p3 = v1 ? *(const float2*)(rowX1 + kB) : z;
            } else {
                p0 = v0 ? *(const float2*)(rowH0 + kA - 96) : z;
                p1 = v1 ? *(const float2*)(rowH1 + kA - 96) : z;
                p2 = v0 ? *(const float2*)(rowH0 + kB - 96) : z;
                p3 = v1 ? *(const float2*)(rowH1 + kB - 96) : z;
            }
            cvt_split(p0, a_hi[0], a_lo[0]);
            cvt_split(p1, a_hi[1], a_lo[1]);
            cvt_split(p2, a_hi[2], a_lo[2]);
            cvt_split(p3, a_hi[3], a_lo[3]);

            int klo = ks * 16 + bk;   // smem-local k for this thread's B fragment
            #pragma unroll
            for (int p = 0; p < 8; p++) {   // 8 n-pair-tiles x 16 cols = full 128
                const __nv_bfloat16* hrow0 = &Bhi[(p * 16 + bn) * BSTRIDE + klo];
                const __nv_bfloat16* hrow1 = &Bhi[(p * 16 + 8 + bn) * BSTRIDE + klo];
                const __nv_bfloat16* lrow0 = &Blo[(p * 16 + bn) * BSTRIDE + klo];
                const __nv_bfloat16* lrow1 = &Blo[(p * 16 + 8 + bn) * BSTRIDE + klo];
                uint32_t bh0 = *(const uint32_t*)(hrow0);
                uint32_t bh1 = *(const uint32_t*)(hrow0 + 8);
                uint32_t bh2 = *(const uint32_t*)(hrow1);
                uint32_t bh3 = *(const uint32_t*)(hrow1 + 8);
                uint32_t bl0 = *(const uint32_t*)(lrow0);
                uint32_t bl1 = *(const uint32_t*)(lrow0 + 8);
                uint32_t bl2 = *(const uint32_t*)(lrow1);
                uint32_t bl3 = *(const uint32_t*)(lrow1 + 8);
                mma16816(C[2 * p],     a_hi, bh0, bh1);
                mma16816(C[2 * p],     a_hi, bl0, bl1);
                mma16816(C[2 * p],     a_lo, bh0, bh1);
                mma16816(C[2 * p + 1], a_hi, bh2, bh3);
                mma16816(C[2 * p + 1], a_hi, bl2, bl3);
                mma16816(C[2 * p + 1], a_lo, bh2, bh3);
            }
        }
    }

    // ---- epilogue: write C to g_q (c0/c1 -> row m0, c2/c3 -> row m0+8) ----
    #pragma unroll
    for (int t = 0; t < 16; t++) {
        int col = t * 8 + tg * 2;
        if (v0) *(float2*)&g_q[(size_t)m0 * 128 + col]       = make_float2(C[t][0], C[t][1]);
        if (v1) *(float2*)&g_q[(size_t)(m0 + 8) * 128 + col] = make_float2(C[t][2], C[t][3]);
    }
}

// ---------------- main: neighbor-sum + eps-GEMV + relu + block mean ----------------
__global__ void __launch_bounds__(256) main_kernel(const float* __restrict__ bias,
                                                   const float* __restrict__ W,
                                                   const float* __restrict__ gin_eps) {
    __shared__ float4 Weps[32][32];
    __shared__ float  bsm[128];
    __shared__ float  zs[8 * 4 * 128];
    int tid = threadIdx.x, lane = tid & 31, wid = tid >> 5;

    for (int idx = tid; idx < 32 * 128; idx += 256) {
        int f = idx >> 7, c = idx & 127;
        ((float*)Weps)[idx] = W[(96 + f) * 128 + c];
    }
    if (tid < 128) bsm[tid] = bias[tid];
    __syncthreads();

    int n = blockIdx.x * 8 + wid;
    float c0 = 1.f + *gin_eps;

    float4 acc = *(const float4*)&g_q[(size_t)n * 128 + 4 * lane];
    acc.x *= c0; acc.y *= c0; acc.z *= c0; acc.w *= c0;

    uint4 selfp = *(const uint4*)&g_eps_pack[n * 4];
    int cnt0 = 0, cnt1 = 0, cnt2 = 0, cnt3 = 0;

    int deg = g_cnt[n];
    if (deg > ADJ_STRIDE) deg = ADJ_STRIDE;
    const int* adj = &g_adj[(size_t)n * ADJ_STRIDE];
    #pragma unroll 4
    for (int e = 0; e < deg; e++) {
        int j = adj[e];
        float4 qv = *(const float4*)&g_q[(size_t)j * 128 + 4 * lane];
        acc.x += qv.x; acc.y += qv.y; acc.z += qv.z; acc.w += qv.w;
        uint4 p = *(const uint4*)&g_eps_pack[j * 4];
        cnt0 += (p.x >> lane) & 1;
        cnt1 += (p.y >> lane) & 1;
        cnt2 += (p.z >> lane) & 1;
        cnt3 += (p.w >> lane) & 1;
    }

    float coeff[4];
    coeff[0] = (float)cnt0 + c0 * (float)((selfp.x >> lane) & 1);
    coeff[1] = (float)cnt1 + c0 * (float)((selfp.y >> lane) & 1);
    coeff[2] = (float)cnt2 + c0 * (float)((selfp.z >> lane) & 1);
    coeff[3] = (float)cnt3 + c0 * (float)((selfp.w >> lane) & 1);

    float4 b4 = ((const float4*)bsm)[lane];
    unsigned long long zA[4], zB[4];
    #pragma unroll
    for (int s = 0; s < 4; s++) {
        zA[s] = f2pack(acc.x + b4.x, acc.y + b4.y);
        zB[s] = f2pack(acc.z + b4.z, acc.w + b4.w);
    }
    #pragma unroll
    for (int f = 0; f < 32; f++) {
        float4 w4 = Weps[f][lane];
        unsigned long long wA = f2pack(w4.x, w4.y), wB = f2pack(w4.z, w4.w);
        #pragma unroll
        for (int s = 0; s < 4; s++) {
            float cf = __shfl_sync(0xffffffffu, coeff[s], f);
            unsigned long long cf2 = f2pack(cf, cf);
            f2fma(zA[s], cf2, wA);
            f2fma(zB[s], cf2, wB);
        }
    }
    #pragma unroll
    for (int s = 0; s < 4; s++) {
        float4 r;
        f2unpack(r.x, r.y, zA[s]);
        f2unpack(r.z, r.w, zB[s]);
        r.x = fmaxf(r.x, 0.f); r.y = fmaxf(r.y, 0.f);
        r.z = fmaxf(r.z, 0.f); r.w = fmaxf(r.w, 0.f);
        ((float4*)zs)[(wid * 4 + s) * 32 + lane] = r;
    }
    __syncthreads();

    for (int p = tid; p < 512; p += 256) {
        float v = 0.f;
        #pragma unroll
        for (int w = 0; w < 8; w++) v += zs[w * 512 + p];
        g_part[(size_t)blockIdx.x * 512 + p] = v;
    }
}

// ---------------- two-stage deterministic mean reduction ----------------
__global__ void reduce1_kernel() {
    int tid = threadIdx.x;
    int b = blockIdx.x;
    float v = 0.f;
    for (int i = b; i < MAIN_BLOCKS; i += 64) v += g_part[(size_t)i * 512 + tid];
    g_part2[b * 512 + tid] = v;
}
__global__ void reduce2_kernel() {
    int tid = threadIdx.x;
    float v = 0.f;
    #pragma unroll
    for (int i = 0; i < 64; i++) v += g_part2[i * 512 + tid];
    g_means[tid] = fmaxf(v * (1.f / (float)N_NODES), 0.f);
}

// ---------------- broadcast means + epsilon tail -> output ----------------
__global__ void bcast_kernel(float4* __restrict__ out,
                             const float4* __restrict__ eps,
                             long long out_size_f4) {
    const int MAIN_F4 = S_SAMP * N_NODES * 32;
    const int EPS_F4  = S_SAMP * N_NODES * 8;
    int idx = blockIdx.x * blockDim.x + threadIdx.x;
    if (idx < MAIN_F4) {
        if ((long long)idx < out_size_f4) {
            int s = idx / (N_NODES * 32);
            int c4 = idx & 31;
            out[idx] = ((const float4*)g_means)[s * 32 + c4];
        }
    } else {
        int k = idx - MAIN_F4;
        if (k < EPS_F4 && (long long)idx < out_size_f4) {
            out[idx] = eps[k];
        }
    }
}

// ---------------- launch ----------------
extern "C" void kernel_launch(void* const* d_in, const int* in_sizes, int n_in,
                              void* d_out, int out_size) {
    const float* X    = (const float*)d_in[0];
    const float* H    = (const float*)d_in[1];
    const float* eps  = (const float*)d_in[2];
    const float* W    = (const float*)d_in[3];
    const float* bias = (const float*)d_in[4];
    const float* geps = (const float*)d_in[5];
    const int*   src  = (const int*)d_in[6];
    const int*   dst  = (const int*)d_in[7];

    zero_cnt_kernel<<<(N_NODES + 255) / 256, 256>>>();
    pack_kernel<<<(S_SAMP * N_NODES + 7) / 8, 256>>>(eps);
    fill_kernel<<<(E_EDGES + 255) / 256, 256>>>(src, dst);
    q_mma_kernel<<<QT_BLOCKS, 256>>>(X, H, W);
    main_kernel<<<MAIN_BLOCKS, 256>>>(bias, W, geps);
    reduce1_kernel<<<64, 512>>>();
    reduce2_kernel<<<1, 512>>>();

    int total_f4 = S_SAMP * N_NODES * 32 + S_SAMP * N_NODES * 8;
    bcast_kernel<<<(total_f4 + 255) / 256, 256>>>((float4*)d_out,
                                                  (const float4*)eps,
                                                  (long long)out_size / 4);
}

// round 11
// speedup vs baseline: 1.7445x; 1.0317x over previous
#include <cuda_runtime.h>
#include <cuda_bf16.h>
#include <cstdint>

#define N_NODES 50000
#define E_EDGES 800000
#define S_SAMP  4
#define ADJ_STRIDE 128
#define MAIN_BLOCKS 6250      // N_NODES / 8
#define QT_TILE 128
#define QT_BLOCKS ((N_NODES + QT_TILE - 1) / QT_TILE)   // 391
#define BSTRIDE 72            // bf16 elements per B smem row (144B; conflict-free frag loads)

// ---------------- scratch (static device globals; no allocs) ----------------
__device__ unsigned int g_eps_pack[S_SAMP * N_NODES];
__device__ int   g_cnt[N_NODES];
__device__ int   g_adj[(size_t)N_NODES * ADJ_STRIDE];
__device__ unsigned int g_qb[(size_t)N_NODES * 64];   // q as bf16x2: [n][64] col-pairs (12.8MB)
__device__ float g_part[(size_t)MAIN_BLOCKS * S_SAMP * 128];
__device__ float g_part2[64 * S_SAMP * 128];
__device__ float g_means[S_SAMP * 128];

// ---------------- f32x2 packed math helpers ----------------
__device__ __forceinline__ unsigned long long f2pack(float lo, float hi) {
    unsigned long long r;
    asm("mov.b64 %0, {%1, %2};" : "=l"(r) : "f"(lo), "f"(hi));
    return r;
}
__device__ __forceinline__ void f2fma(unsigned long long& d, unsigned long long a, unsigned long long b) {
    asm("fma.rn.f32x2 %0, %1, %2, %0;" : "+l"(d) : "l"(a), "l"(b));
}
__device__ __forceinline__ void f2unpack(float& lo, float& hi, unsigned long long v) {
    asm("mov.b64 {%0, %1}, %2;" : "=f"(lo), "=f"(hi) : "l"(v));
}

// split fp32 pair -> (hi bf16x2, lo bf16x2)
__device__ __forceinline__ void cvt_split(float2 v, uint32_t& hi, uint32_t& lo) {
    __nv_bfloat162 h2 = __floats2bfloat162_rn(v.x, v.y);
    float fx = __bfloat162float(h2.x), fy = __bfloat162float(h2.y);
    __nv_bfloat162 l2 = __floats2bfloat162_rn(v.x - fx, v.y - fy);
    hi = *(uint32_t*)&h2;
    lo = *(uint32_t*)&l2;
}

__device__ __forceinline__ void mma16816(float* c, const uint32_t* a, uint32_t b0, uint32_t b1) {
    asm volatile("mma.sync.aligned.m16n8k16.row.col.f32.bf16.bf16.f32 "
                 "{%0,%1,%2,%3}, {%4,%5,%6,%7}, {%8,%9}, {%0,%1,%2,%3};"
                 : "+f"(c[0]), "+f"(c[1]), "+f"(c[2]), "+f"(c[3])
                 : "r"(a[0]), "r"(a[1]), "r"(a[2]), "r"(a[3]), "r"(b0), "r"(b1));
}

// ---------------- setup kernels ----------------
// pack epsilon bits AND zero the degree counters (merged; independent data)
__global__ void pack_zero_kernel(const float* __restrict__ eps) {
    int gid = blockIdx.x * blockDim.x + threadIdx.x;
    if (gid < N_NODES) g_cnt[gid] = 0;
    int g = blockIdx.x * 8 + (threadIdx.x >> 5);
    int lane = threadIdx.x & 31;
    if (g >= S_SAMP * N_NODES) return;
    int s = g / N_NODES;
    int n = g - s * N_NODES;
    float v = eps[(size_t)g * 32 + lane];
    unsigned m = __ballot_sync(0xffffffffu, v > 0.5f);
    if (lane == 0) g_eps_pack[n * 4 + s] = m;
}

__global__ void fill_kernel(const int* __restrict__ src, const int* __restrict__ dst) {
    int e = blockIdx.x * blockDim.x + threadIdx.x;
    if (e < E_EDGES) {
        int d = dst[e];
        int slot = atomicAdd(&g_cnt[d], 1);
        if (slot < ADJ_STRIDE)
            g_adj[(size_t)d * ADJ_STRIDE + slot] = src[e];
    }
}

// ---------------- q = [X,h] @ W_shared via mma.sync split-bf16 ----------------
// 128 nodes/CTA, 8 warps x 16 rows x all 128 cols. Output stored as bf16x2.
__global__ void __launch_bounds__(256) q_mma_kernel(const float* __restrict__ X,
                                                    const float* __restrict__ H,
                                                    const float* __restrict__ W) {
    __shared__ __nv_bfloat16 Bhi[128 * BSTRIDE];   // 18432 B
    __shared__ __nv_bfloat16 Blo[128 * BSTRIDE];   // 18432 B

    int tid = threadIdx.x, lane = tid & 31, wid = tid >> 5;
    int tg = lane & 3;
    int node0 = blockIdx.x * QT_TILE;
    int m0 = node0 + wid * 16 + (lane >> 2);   // row for c0/c1; m0+8 for c2/c3
    bool v0 = m0 < N_NODES, v1 = (m0 + 8) < N_NODES;

    const float* rowX0 = X + (size_t)m0 * 96;
    const float* rowH0 = H + (size_t)m0 * 32;
    const float* rowX1 = rowX0 + 8 * 96;
    const float* rowH1 = rowH0 + 8 * 32;

    float C[16][4];    // 16 n-tiles of 8 cols -> full 128 output columns
    #pragma unroll
    for (int t = 0; t < 16; t++)
        #pragma unroll
        for (int i = 0; i < 4; i++) C[t][i] = 0.f;

    int bn = lane >> 2;        // n-within-8 for B fragments
    int bk = (lane & 3) * 2;   // k-pair base for B fragments

    for (int half = 0; half < 2; half++) {
        __syncthreads();
        // stage B[n][k] = W[wrow(k)][n] for k in [half*64, half*64+64), split hi/lo
        for (int idx = tid; idx < 32 * 128; idx += 256) {
            int kp = idx >> 7, n = idx & 127;
            int k = half * 64 + kp * 2;
            int wr0 = (k < 96) ? k : (k + 32);          // skip eps rows 96..127 of W
            int wr1 = (k + 1 < 96) ? (k + 1) : (k + 33);
            float2 v = make_float2(W[wr0 * 128 + n], W[wr1 * 128 + n]);
            uint32_t hi, lo;
            cvt_split(v, hi, lo);
            *(uint32_t*)&Bhi[n * BSTRIDE + kp * 2] = hi;
            *(uint32_t*)&Blo[n * BSTRIDE + kp * 2] = lo;
        }
        __syncthreads();

        #pragma unroll
        for (int ks = 0; ks < 4; ks++) {
            int k0 = half * 64 + ks * 16;
            // ---- A fragments from global (split hi/lo), per mma spec ----
            uint32_t a_hi[4], a_lo[4];
            int kA = k0 + tg * 2;
            int kB = kA + 8;
            float2 z = make_float2(0.f, 0.f);
            float2 p0, p1, p2, p3;
            if (k0 < 96) {   // whole 16-wide k-slab inside X (k0 mult of 16; 96 = 6*16)
                p0 = v0 ? *(const float2*)(rowX0 + kA) : z;
                p1 = v1 ? *(const float2*)(rowX1 + kA) : z;
                p2 = v0 ? *(const float2*)(rowX0 + kB) : z;
                p3 = v1 ? *(const float2*)(rowX1 + kB) : z;
            } else {
                p0 = v0 ? *(const float2*)(rowH0 + kA - 96) : z;
                p1 = v1 ? *(const float2*)(rowH1 + kA - 96) : z;
                p2 = v0 ? *(const float2*)(rowH0 + kB - 96) : z;
                p3 = v1 ? *(const float2*)(rowH1 + kB - 96) : z;
            }
            cvt_split(p0, a_hi[0], a_lo[0]);
            cvt_split(p1, a_hi[1], a_lo[1]);
            cvt_split(p2, a_hi[2], a_lo[2]);
            cvt_split(p3, a_hi[3], a_lo[3]);

            int klo = ks * 16 + bk;   // smem-local k for this thread's B fragment
            #pragma unroll
            for (int p = 0; p < 8; p++) {   // 8 n-pair-tiles x 16 cols = full 128
                const __nv_bfloat16* hrow0 = &Bhi[(p * 16 + bn) * BSTRIDE + klo];
                const __nv_bfloat16* hrow1 = &Bhi[(p * 16 + 8 + bn) * BSTRIDE + klo];
                const __nv_bfloat16* lrow0 = &Blo[(p * 16 + bn) * BSTRIDE + klo];
                const __nv_bfloat16* lrow1 = &Blo[(p * 16 + 8 + bn) * BSTRIDE + klo];
                uint32_t bh0 = *(const uint32_t*)(hrow0);
                uint32_t bh1 = *(const uint32_t*)(hrow0 + 8);
                uint32_t bh2 = *(const uint32_t*)(hrow1);
                uint32_t bh3 = *(const uint32_t*)(hrow1 + 8);
                uint32_t bl0 = *(const uint32_t*)(lrow0);
                uint32_t bl1 = *(const uint32_t*)(lrow0 + 8);
                uint32_t bl2 = *(const uint32_t*)(lrow1);
                uint32_t bl3 = *(const uint32_t*)(lrow1 + 8);
                mma16816(C[2 * p],     a_hi, bh0, bh1);
                mma16816(C[2 * p],     a_hi, bl0, bl1);
                mma16816(C[2 * p],     a_lo, bh0, bh1);
                mma16816(C[2 * p + 1], a_hi, bh2, bh3);
                mma16816(C[2 * p + 1], a_hi, bl2, bl3);
                mma16816(C[2 * p + 1], a_lo, bh2, bh3);
            }
        }
    }

    // ---- epilogue: write C as bf16x2 to g_qb ----
    #pragma unroll
    for (int t = 0; t < 16; t++) {
        int pairidx = t * 4 + tg;   // col pair (t*8+tg*2)/2
        if (v0) {
            __nv_bfloat162 b2 = __floats2bfloat162_rn(C[t][0], C[t][1]);
            g_qb[(size_t)m0 * 64 + pairidx] = *(uint32_t*)&b2;
        }
        if (v1) {
            __nv_bfloat162 b2 = __floats2bfloat162_rn(C[t][2], C[t][3]);
            g_qb[(size_t)(m0 + 8) * 64 + pairidx] = *(uint32_t*)&b2;
        }
    }
}

// ---------------- main: neighbor-sum + eps-GEMV + relu + block mean ----------------
// block: 256 threads = 8 warps = 8 nodes; q gathered as bf16x2 (half the bytes)
__global__ void __launch_bounds__(256) main_kernel(const float* __restrict__ bias,
                                                   const float* __restrict__ W,
                                                   const float* __restrict__ gin_eps) {
    __shared__ float4 Weps[32][32];
    __shared__ float  bsm[128];
    __shared__ float  zs[8 * 4 * 128];
    int tid = threadIdx.x, lane = tid & 31, wid = tid >> 5;

    for (int idx = tid; idx < 32 * 128; idx += 256) {
        int f = idx >> 7, c = idx & 127;
        ((float*)Weps)[idx] = W[(96 + f) * 128 + c];
    }
    if (tid < 128) bsm[tid] = bias[tid];
    __syncthreads();

    int n = blockIdx.x * 8 + wid;
    float c0 = 1.f + *gin_eps;

    // self term (bf16 q)
    uint2 sp = *(const uint2*)&g_qb[(size_t)n * 64 + lane * 2];
    float2 s0 = __bfloat1622float2(*(__nv_bfloat162*)&sp.x);
    float2 s1 = __bfloat1622float2(*(__nv_bfloat162*)&sp.y);
    float4 acc = make_float4(c0 * s0.x, c0 * s0.y, c0 * s1.x, c0 * s1.y);

    uint4 selfp = *(const uint4*)&g_eps_pack[n * 4];
    int cnt0 = 0, cnt1 = 0, cnt2 = 0, cnt3 = 0;

    int deg = g_cnt[n];
    if (deg > ADJ_STRIDE) deg = ADJ_STRIDE;
    const int* adj = &g_adj[(size_t)n * ADJ_STRIDE];
    #pragma unroll 4
    for (int e = 0; e < deg; e++) {
        int j = adj[e];
        uint2 qp = *(const uint2*)&g_qb[(size_t)j * 64 + lane * 2];
        float2 q0 = __bfloat1622float2(*(__nv_bfloat162*)&qp.x);
        float2 q1 = __bfloat1622float2(*(__nv_bfloat162*)&qp.y);
        acc.x += q0.x; acc.y += q0.y; acc.z += q1.x; acc.w += q1.y;
        uint4 p = *(const uint4*)&g_eps_pack[j * 4];
        cnt0 += (p.x >> lane) & 1;
        cnt1 += (p.y >> lane) & 1;
        cnt2 += (p.z >> lane) & 1;
        cnt3 += (p.w >> lane) & 1;
    }

    float coeff[4];
    coeff[0] = (float)cnt0 + c0 * (float)((selfp.x >> lane) & 1);
    coeff[1] = (float)cnt1 + c0 * (float)((selfp.y >> lane) & 1);
    coeff[2] = (float)cnt2 + c0 * (float)((selfp.z >> lane) & 1);
    coeff[3] = (float)cnt3 + c0 * (float)((selfp.w >> lane) & 1);

    float4 b4 = ((const float4*)bsm)[lane];
    unsigned long long zA[4], zB[4];
    #pragma unroll
    for (int s = 0; s < 4; s++) {
        zA[s] = f2pack(acc.x + b4.x, acc.y + b4.y);
        zB[s] = f2pack(acc.z + b4.z, acc.w + b4.w);
    }
    #pragma unroll
    for (int f = 0; f < 32; f++) {
        float4 w4 = Weps[f][lane];
        unsigned long long wA = f2pack(w4.x, w4.y), wB = f2pack(w4.z, w4.w);
        #pragma unroll
        for (int s = 0; s < 4; s++) {
            float cf = __shfl_sync(0xffffffffu, coeff[s], f);
            unsigned long long cf2 = f2pack(cf, cf);
            f2fma(zA[s], cf2, wA);
            f2fma(zB[s], cf2, wB);
        }
    }
    #pragma unroll
    for (int s = 0; s < 4; s++) {
        float4 r;
        f2unpack(r.x, r.y, zA[s]);
        f2unpack(r.z, r.w, zB[s]);
        r.x = fmaxf(r.x, 0.f); r.y = fmaxf(r.y, 0.f);
        r.z = fmaxf(r.z, 0.f); r.w = fmaxf(r.w, 0.f);
        ((float4*)zs)[(wid * 4 + s) * 32 + lane] = r;
    }
    __syncthreads();

    for (int p = tid; p < 512; p += 256) {
        float v = 0.f;
        #pragma unroll
        for (int w = 0; w < 8; w++) v += zs[w * 512 + p];
        g_part[(size_t)blockIdx.x * 512 + p] = v;
    }
}

// ---------------- two-stage deterministic mean reduction ----------------
__global__ void reduce1_kernel() {
    int tid = threadIdx.x;
    int b = blockIdx.x;
    float v = 0.f;
    for (int i = b; i < MAIN_BLOCKS; i += 64) v += g_part[(size_t)i * 512 + tid];
    g_part2[b * 512 + tid] = v;
}
__global__ void reduce2_kernel() {
    int tid = threadIdx.x;
    float v = 0.f;
    #pragma unroll
    for (int i = 0; i < 64; i++) v += g_part2[i * 512 + tid];
    g_means[tid] = fmaxf(v * (1.f / (float)N_NODES), 0.f);
}

// ---------------- broadcast means + epsilon tail -> output ----------------
__global__ void bcast_kernel(float4* __restrict__ out,
                             const float4* __restrict__ eps,
                             long long out_size_f4) {
    const int MAIN_F4 = S_SAMP * N_NODES * 32;
    const int EPS_F4  = S_SAMP * N_NODES * 8;
    int idx = blockIdx.x * blockDim.x + threadIdx.x;
    if (idx < MAIN_F4) {
        if ((long long)idx < out_size_f4) {
            int s = idx / (N_NODES * 32);
            int c4 = idx & 31;
            out[idx] = ((const float4*)g_means)[s * 32 + c4];
        }
    } else {
        int k = idx - MAIN_F4;
        if (k < EPS_F4 && (long long)idx < out_size_f4) {
            out[idx] = eps[k];
        }
    }
}

// ---------------- launch ----------------
extern "C" void kernel_launch(void* const* d_in, const int* in_sizes, int n_in,
                              void* d_out, int out_size) {
    const float* X    = (const float*)d_in[0];
    const float* H    = (const float*)d_in[1];
    const float* eps  = (const float*)d_in[2];
    const float* W    = (const float*)d_in[3];
    const float* bias = (const float*)d_in[4];
    const float* geps = (const float*)d_in[5];
    const int*   src  = (const int*)d_in[6];
    const int*   dst  = (const int*)d_in[7];

    pack_zero_kernel<<<(S_SAMP * N_NODES + 7) / 8, 256>>>(eps);
    fill_kernel<<<(E_EDGES + 255) / 256, 256>>>(src, dst);
    q_mma_kernel<<<QT_BLOCKS, 256>>>(X, H, W);
    main_kernel<<<MAIN_BLOCKS, 256>>>(bias, W, geps);
    reduce1_kernel<<<64, 512>>>();
    reduce2_kernel<<<1, 512>>>();

    int total_f4 = S_SAMP * N_NODES * 32 + S_SAMP * N_NODES * 8;
    bcast_kernel<<<(total_f4 + 255) / 256, 256>>>((float4*)d_out,
                                                  (const float4*)eps,
                                                  (long long)out_size / 4);
}

// round 14
// speedup vs baseline: 1.7799x; 1.0203x over previous
#include <cuda_runtime.h>
#include <cuda_bf16.h>
#include <cstdint>

#define N_NODES 50000
#define E_EDGES 800000
#define S_SAMP  4
#define ADJ_STRIDE 128
#define GATHER_BLOCKS 6250    // N_NODES / 8
#define QT_TILE 128
#define QT_BLOCKS ((N_NODES + QT_TILE - 1) / QT_TILE)   // 391
#define ZB_BLOCKS QT_BLOCKS                             // 391 (128 nodes per CTA)
#define PART_ROWS (ZB_BLOCKS * 8)                       // 3128
#define BSTRIDE 72            // q_mma B row stride (bf16 elems)
#define BS2 40                // z_mma Weps row stride (bf16 elems), conflict-free

// ---------------- scratch (static device globals; no allocs) ----------------
__device__ unsigned int g_eps_pack[S_SAMP * N_NODES];
__device__ int   g_cnt[N_NODES];
__device__ int   g_adj[(size_t)N_NODES * ADJ_STRIDE];
__device__ unsigned int g_qb[(size_t)N_NODES * 64];    // q bf16x2 [n][64 col-pairs]
__device__ unsigned int g_acc2[(size_t)N_NODES * 64];  // aggregated q-sums, bf16x2
__device__ unsigned int g_cntp[(size_t)N_NODES * 32];  // neighbor eps counts, 4x u8 per u32
__device__ float g_part[(size_t)PART_ROWS * S_SAMP * 128];
__device__ float g_part2[64 * S_SAMP * 128];
__device__ float g_means[S_SAMP * 128];

// ---------------- helpers ----------------
__device__ __forceinline__ float2 bf2_to_f2(uint32_t v) {
    return make_float2(__uint_as_float(v << 16), __uint_as_float(v & 0xFFFF0000u));
}

// split fp32 pair -> (hi bf16x2, lo bf16x2)
__device__ __forceinline__ void cvt_split(float2 v, uint32_t& hi, uint32_t& lo) {
    __nv_bfloat162 h2 = __floats2bfloat162_rn(v.x, v.y);
    float fx = __bfloat162float(h2.x), fy = __bfloat162float(h2.y);
    __nv_bfloat162 l2 = __floats2bfloat162_rn(v.x - fx, v.y - fy);
    hi = *(uint32_t*)&h2;
    lo = *(uint32_t*)&l2;
}

__device__ __forceinline__ void mma16816(float* c, const uint32_t* a, uint32_t b0, uint32_t b1) {
    asm volatile("mma.sync.aligned.m16n8k16.row.col.f32.bf16.bf16.f32 "
                 "{%0,%1,%2,%3}, {%4,%5,%6,%7}, {%8,%9}, {%0,%1,%2,%3};"
                 : "+f"(c[0]), "+f"(c[1]), "+f"(c[2]), "+f"(c[3])
                 : "r"(a[0]), "r"(a[1]), "r"(a[2]), "r"(a[3]), "r"(b0), "r"(b1));
}

// ---------------- setup kernels ----------------
__global__ void pack_zero_kernel(const float* __restrict__ eps) {
    int gid = blockIdx.x * blockDim.x + threadIdx.x;
    if (gid < N_NODES) g_cnt[gid] = 0;
    int g = blockIdx.x * 8 + (threadIdx.x >> 5);
    int lane = threadIdx.x & 31;
    if (g >= S_SAMP * N_NODES) return;
    int s = g / N_NODES;
    int n = g - s * N_NODES;
    float v = eps[(size_t)g * 32 + lane];
    unsigned m = __ballot_sync(0xffffffffu, v > 0.5f);
    if (lane == 0) g_eps_pack[n * 4 + s] = m;
}

__global__ void fill_kernel(const int* __restrict__ src, const int* __restrict__ dst) {
    int e = blockIdx.x * blockDim.x + threadIdx.x;
    if (e < E_EDGES) {
        int d = dst[e];
        int slot = atomicAdd(&g_cnt[d], 1);
        if (slot < ADJ_STRIDE)
            g_adj[(size_t)d * ADJ_STRIDE + slot] = src[e];
    }
}

// ---------------- q = [X,h] @ W_shared via mma.sync split-bf16 ----------------
__global__ void __launch_bounds__(256) q_mma_kernel(const float* __restrict__ X,
                                                    const float* __restrict__ H,
                                                    const float* __restrict__ W) {
    __shared__ __nv_bfloat16 Bhi[128 * BSTRIDE];
    __shared__ __nv_bfloat16 Blo[128 * BSTRIDE];

    int tid = threadIdx.x, lane = tid & 31, wid = tid >> 5;
    int tg = lane & 3;
    int node0 = blockIdx.x * QT_TILE;
    int m0 = node0 + wid * 16 + (lane >> 2);
    bool v0 = m0 < N_NODES, v1 = (m0 + 8) < N_NODES;

    const float* rowX0 = X + (size_t)m0 * 96;
    const float* rowH0 = H + (size_t)m0 * 32;
    const float* rowX1 = rowX0 + 8 * 96;
    const float* rowH1 = rowH0 + 8 * 32;

    float C[16][4];
    #pragma unroll
    for (int t = 0; t < 16; t++)
        #pragma unroll
        for (int i = 0; i < 4; i++) C[t][i] = 0.f;

    int bn = lane >> 2;
    int bk = (lane & 3) * 2;

    for (int half = 0; half < 2; half++) {
        __syncthreads();
        for (int idx = tid; idx < 32 * 128; idx += 256) {
            int kp = idx >> 7, n = idx & 127;
            int k = half * 64 + kp * 2;
            int wr0 = (k < 96) ? k : (k + 32);
            int wr1 = (k + 1 < 96) ? (k + 1) : (k + 33);
            float2 v = make_float2(W[wr0 * 128 + n], W[wr1 * 128 + n]);
            uint32_t hi, lo;
            cvt_split(v, hi, lo);
            *(uint32_t*)&Bhi[n * BSTRIDE + kp * 2] = hi;
            *(uint32_t*)&Blo[n * BSTRIDE + kp * 2] = lo;
        }
        __syncthreads();

        #pragma unroll
        for (int ks = 0; ks < 4; ks++) {
            int k0 = half * 64 + ks * 16;
            uint32_t a_hi[4], a_lo[4];
            int kA = k0 + tg * 2;
            int kB = kA + 8;
            float2 z = make_float2(0.f, 0.f);
            float2 p0, p1, p2, p3;
            if (k0 < 96) {
                p0 = v0 ? *(const float2*)(rowX0 + kA) : z;
                p1 = v1 ? *(const float2*)(rowX1 + kA) : z;
                p2 = v0 ? *(const float2*)(rowX0 + kB) : z;
                p3 = v1 ? *(const float2*)(rowX1 + kB) : z;
            } else {
                p0 = v0 ? *(const float2*)(rowH0 + kA - 96) : z;
                p1 = v1 ? *(const float2*)(rowH1 + kA - 96) : z;
                p2 = v0 ? *(const float2*)(rowH0 + kB - 96) : z;
                p3 = v1 ? *(const float2*)(rowH1 + kB - 96) : z;
            }
            cvt_split(p0, a_hi[0], a_lo[0]);
            cvt_split(p1, a_hi[1], a_lo[1]);
            cvt_split(p2, a_hi[2], a_lo[2]);
            cvt_split(p3, a_hi[3], a_lo[3]);

            int klo = ks * 16 + bk;
            #pragma unroll
            for (int p = 0; p < 8; p++) {
                const __nv_bfloat16* hrow0 = &Bhi[(p * 16 + bn) * BSTRIDE + klo];
                const __nv_bfloat16* hrow1 = &Bhi[(p * 16 + 8 + bn) * BSTRIDE + klo];
                const __nv_bfloat16* lrow0 = &Blo[(p * 16 + bn) * BSTRIDE + klo];
                const __nv_bfloat16* lrow1 = &Blo[(p * 16 + 8 + bn) * BSTRIDE + klo];
                uint32_t bh0 = *(const uint32_t*)(hrow0);
                uint32_t bh1 = *(const uint32_t*)(hrow0 + 8);
                uint32_t bh2 = *(const uint32_t*)(hrow1);
                uint32_t bh3 = *(const uint32_t*)(hrow1 + 8);
                uint32_t bl0 = *(const uint32_t*)(lrow0);
                uint32_t bl1 = *(const uint32_t*)(lrow0 + 8);
                uint32_t bl2 = *(const uint32_t*)(lrow1);
                uint32_t bl3 = *(const uint32_t*)(lrow1 + 8);
                mma16816(C[2 * p],     a_hi, bh0, bh1);
                mma16816(C[2 * p],     a_hi, bl0, bl1);
                mma16816(C[2 * p],     a_lo, bh0, bh1);
                mma16816(C[2 * p + 1], a_hi, bh2, bh3);
                mma16816(C[2 * p + 1], a_hi, bl2, bl3);
                mma16816(C[2 * p + 1], a_lo, bh2, bh3);
            }
        }
    }

    #pragma unroll
    for (int t = 0; t < 16; t++) {
        int pairidx = t * 4 + tg;
        if (v0) {
            __nv_bfloat162 b2 = __floats2bfloat162_rn(C[t][0], C[t][1]);
            g_qb[(size_t)m0 * 64 + pairidx] = *(uint32_t*)&b2;
        }
        if (v1) {
            __nv_bfloat162 b2 = __floats2bfloat162_rn(C[t][2], C[t][3]);
            g_qb[(size_t)(m0 + 8) * 64 + pairidx] = *(uint32_t*)&b2;
        }
    }
}

// ---------------- gather: neighbor-sum of q + packed eps counts ----------------
// warp = node; no smem, no shfl. Writes acc (bf16x2) + counts (4x u8).
__global__ void __launch_bounds__(256) gather_kernel(const float* __restrict__ gin_eps) {
    int lane = threadIdx.x & 31, wid = threadIdx.x >> 5;
    int n = blockIdx.x * 8 + wid;          // exact: 6250*8 == N_NODES
    float c0 = 1.f + *gin_eps;

    uint2 sp = *(const uint2*)&g_qb[(size_t)n * 64 + lane * 2];
    float2 s0 = bf2_to_f2(sp.x), s1 = bf2_to_f2(sp.y);
    float4 acc = make_float4(c0 * s0.x, c0 * s0.y, c0 * s1.x, c0 * s1.y);

    unsigned cntp = 0;
    int deg = g_cnt[n];
    if (deg > ADJ_STRIDE) deg = ADJ_STRIDE;
    const int* adj = &g_adj[(size_t)n * ADJ_STRIDE];
    #pragma unroll 4
    for (int e = 0; e < deg; e++) {
        int j = adj[e];
        uint2 qp = *(const uint2*)&g_qb[(size_t)j * 64 + lane * 2];
        float2 q0 = bf2_to_f2(qp.x), q1 = bf2_to_f2(qp.y);
        acc.x += q0.x; acc.y += q0.y; acc.z += q1.x; acc.w += q1.y;
        uint4 p = *(const uint4*)&g_eps_pack[j * 4];
        unsigned b = ((p.x >> lane) & 1u)
                   | (((p.y >> lane) & 1u) << 8)
                   | (((p.z >> lane) & 1u) << 16)
                   | (((p.w >> lane) & 1u) << 24);
        cntp += b;
    }

    __nv_bfloat162 o0 = __floats2bfloat162_rn(acc.x, acc.y);
    __nv_bfloat162 o1 = __floats2bfloat162_rn(acc.z, acc.w);
    *(uint2*)&g_acc2[(size_t)n * 64 + lane * 2] = make_uint2(*(uint32_t*)&o0, *(uint32_t*)&o1);
    g_cntp[(size_t)n * 32 + lane] = cntp;
}

// ---------------- z = acc + Coeff@Weps + bias, relu, row-fold -> g_part ----------------
// 128 nodes/CTA, q_mma-style fragments. Counts are bf16-exact integers.
__global__ void __launch_bounds__(256) z_mma_kernel(const float* __restrict__ W,
                                                    const float* __restrict__ bias,
                                                    const float* __restrict__ gin_eps) {
    __shared__ __nv_bfloat16 Wbh[128 * BS2];   // [col][feat] hi  (10240 B)
    __shared__ __nv_bfloat16 Wbl[128 * BS2];

    int tid = threadIdx.x, lane = tid & 31, wid = tid >> 5;
    int tg = lane & 3, bn = lane >> 2;
    int node0 = blockIdx.x * 128;
    int m0 = node0 + wid * 16 + bn;
    bool v0 = m0 < N_NODES, v1 = (m0 + 8) < N_NODES;
    float c0 = 1.f + *gin_eps;
    int kAb = tg * 2;

    // stage Weps^T [col][feat], hi/lo split
    for (int idx = tid; idx < 128 * 32; idx += 256) {
        int col = idx >> 5, f = idx & 31;
        float w = W[(96 + f) * 128 + col];
        __nv_bfloat16 h = __float2bfloat16(w);
        Wbh[col * BS2 + f] = h;
        Wbl[col * BS2 + f] = __float2bfloat16(w - __bfloat162float(h));
    }

    // raw count pairs: rows m0, m0+8; feat offsets {0,8,16,24}+kAb
    uint2 cp0[4], cp1[4];
    #pragma unroll
    for (int o = 0; o < 4; o++) {
        cp0[o] = v0 ? *(const uint2*)&g_cntp[(size_t)m0 * 32 + o * 8 + kAb] : make_uint2(0u, 0u);
        cp1[o] = v1 ? *(const uint2*)&g_cntp[(size_t)(m0 + 8) * 32 + o * 8 + kAb] : make_uint2(0u, 0u);
    }
    uint4 sb0 = v0 ? *(const uint4*)&g_eps_pack[m0 * 4] : make_uint4(0u, 0u, 0u, 0u);
    uint4 sb1 = v1 ? *(const uint4*)&g_eps_pack[(m0 + 8) * 4] : make_uint4(0u, 0u, 0u, 0u);

    // acc (bf16->f32) + bias, held in regs
    float accb0[16][2], accb1[16][2];
    #pragma unroll
    for (int t = 0; t < 16; t++) {
        int col = t * 8 + kAb;
        float bv0 = bias[col], bv1 = bias[col + 1];
        uint32_t a0 = v0 ? g_acc2[(size_t)m0 * 64 + (col >> 1)] : 0u;
        uint32_t a1 = v1 ? g_acc2[(size_t)(m0 + 8) * 64 + (col >> 1)] : 0u;
        float2 f0 = bf2_to_f2(a0), f1 = bf2_to_f2(a1);
        accb0[t][0] = f0.x + bv0; accb0[t][1] = f0.y + bv1;
        accb1[t][0] = f1.x + bv0; accb1[t][1] = f1.y + bv1;
    }
    __syncthreads();

    #pragma unroll 1
    for (int s = 0; s < 4; s++) {
        unsigned sw0 = (s == 0) ? sb0.x : (s == 1) ? sb0.y : (s == 2) ? sb0.z : sb0.w;
        unsigned sw1 = (s == 0) ? sb1.x : (s == 1) ? sb1.y : (s == 2) ? sb1.z : sb1.w;
        int sh = s * 8;

        float C[16][4];
        #pragma unroll
        for (int t = 0; t < 16; t++) { C[t][0] = C[t][1] = C[t][2] = C[t][3] = 0.f; }

        #pragma unroll
        for (int ks = 0; ks < 2; ks++) {
            uint32_t a_hi[4], a_lo[4];
            #pragma unroll
            for (int half = 0; half < 2; half++) {
                int o = ks * 2 + half;
                int fb = ks * 16 + half * 8 + kAb;
                {
                    float cf0 = (float)((cp0[o].x >> sh) & 0xFFu) + c0 * (float)((sw0 >> fb) & 1u);
                    float cf1 = (float)((cp0[o].y >> sh) & 0xFFu) + c0 * (float)((sw0 >> (fb + 1)) & 1u);
                    cvt_split(make_float2(cf0, cf1), a_hi[half * 2], a_lo[half * 2]);
                }
                {
                    float cf0 = (float)((cp1[o].x >> sh) & 0xFFu) + c0 * (float)((sw1 >> fb) & 1u);
                    float cf1 = (float)((cp1[o].y >> sh) & 0xFFu) + c0 * (float)((sw1 >> (fb + 1)) & 1u);
                    cvt_split(make_float2(cf0, cf1), a_hi[half * 2 + 1], a_lo[half * 2 + 1]);
                }
            }

            int klo = ks * 16 + kAb;
            #pragma unroll
            for (int p = 0; p < 8; p++) {
                const __nv_bfloat16* h0 = &Wbh[(p * 16 + bn) * BS2 + klo];
                const __nv_bfloat16* h1 = &Wbh[(p * 16 + 8 + bn) * BS2 + klo];
                const __nv_bfloat16* l0 = &Wbl[(p * 16 + bn) * BS2 + klo];
                const __nv_bfloat16* l1 = &Wbl[(p * 16 + 8 + bn) * BS2 + klo];
                uint32_t bh0 = *(const uint32_t*)h0, bh1 = *(const uint32_t*)(h0 + 8);
                uint32_t bh2 = *(const uint32_t*)h1, bh3 = *(const uint32_t*)(h1 + 8);
                uint32_t bl0 = *(const uint32_t*)l0, bl1 = *(const uint32_t*)(l0 + 8);
                uint32_t bl2 = *(const uint32_t*)l1, bl3 = *(const uint32_t*)(l1 + 8);
                mma16816(C[2 * p],     a_hi, bh0, bh1);
                mma16816(C[2 * p],     a_hi, bl0, bl1);
                mma16816(C[2 * p],     a_lo, bh0, bh1);
                mma16816(C[2 * p + 1], a_hi, bh2, bh3);
                mma16816(C[2 * p + 1], a_hi, bl2, bl3);
                mma16816(C[2 * p + 1], a_lo, bh2, bh3);
            }
        }

        // epilogue: relu + fold rows + deterministic per-warp partials
        #pragma unroll
        for (int t = 0; t < 16; t++) {
            float r0 = 0.f, r1 = 0.f;
            if (v0) {
                r0 += fmaxf(C[t][0] + accb0[t][0], 0.f);
                r1 += fmaxf(C[t][1] + accb0[t][1], 0.f);
            }
            if (v1) {
                r0 += fmaxf(C[t][2] + accb1[t][0], 0.f);
                r1 += fmaxf(C[t][3] + accb1[t][1], 0.f);
            }
            #pragma unroll
            for (int d = 4; d < 32; d <<= 1) {
                r0 += __shfl_xor_sync(0xffffffffu, r0, d);
                r1 += __shfl_xor_sync(0xffffffffu, r1, d);
            }
            if (lane < 4) {
                size_t row = (size_t)blockIdx.x * 8 + wid;
                *(float2*)&g_part[row * 512 + s * 128 + t * 8 + lane * 2] = make_float2(r0, r1);
            }
        }
    }
}

// ---------------- two-stage deterministic mean reduction ----------------
__global__ void reduce1_kernel() {
    int tid = threadIdx.x;
    int b = blockIdx.x;
    float v = 0.f;
    for (int i = b; i < PART_ROWS; i += 64) v += g_part[(size_t)i * 512 + tid];
    g_part2[b * 512 + tid] = v;
}
__global__ void reduce2_kernel() {
    int tid = threadIdx.x;
    float v = 0.f;
    #pragma unroll
    for (int i = 0; i < 64; i++) v += g_part2[i * 512 + tid];
    g_means[tid] = fmaxf(v * (1.f / (float)N_NODES), 0.f);
}

// ---------------- broadcast means + epsilon tail -> output ----------------
__global__ void bcast_kernel(float4* __restrict__ out,
                             const float4* __restrict__ eps,
                             long long out_size_f4) {
    const int MAIN_F4 = S_SAMP * N_NODES * 32;
    const int EPS_F4  = S_SAMP * N_NODES * 8;
    int idx = blockIdx.x * blockDim.x + threadIdx.x;
    if (idx < MAIN_F4) {
        if ((long long)idx < out_size_f4) {
            int s = idx / (N_NODES * 32);
            int c4 = idx & 31;
            out[idx] = ((const float4*)g_means)[s * 32 + c4];
        }
    } else {
        int k = idx - MAIN_F4;
        if (k < EPS_F4 && (long long)idx < out_size_f4) {
            out[idx] = eps[k];
        }
    }
}

// ---------------- launch ----------------
extern "C" void kernel_launch(void* const* d_in, const int* in_sizes, int n_in,
                              void* d_out, int out_size) {
    const float* X    = (const float*)d_in[0];
    const float* H    = (const float*)d_in[1];
    const float* eps  = (const float*)d_in[2];
    const float* W    = (const float*)d_in[3];
    const float* bias = (const float*)d_in[4];
    const float* geps = (const float*)d_in[5];
    const int*   src  = (const int*)d_in[6];
    const int*   dst  = (const int*)d_in[7];

    pack_zero_kernel<<<(S_SAMP * N_NODES + 7) / 8, 256>>>(eps);
    fill_kernel<<<(E_EDGES + 255) / 256, 256>>>(src, dst);
    q_mma_kernel<<<QT_BLOCKS, 256>>>(X, H, W);
    gather_kernel<<<GATHER_BLOCKS, 256>>>(geps);
    z_mma_kernel<<<ZB_BLOCKS, 256>>>(W, bias, geps);
    reduce1_kernel<<<64, 512>>>();
    reduce2_kernel<<<1, 512>>>();

    int total_f4 = S_SAMP * N_NODES * 32 + S_SAMP * N_NODES * 8;
    bcast_kernel<<<(total_f4 + 255) / 256, 256>>>((float4*)d_out,
                                                  (const float4*)eps,
                                                  (long long)out_size / 4);
}

// round 16
// speedup vs baseline: 2.1072x; 1.1839x over previous
#include <cuda_runtime.h>
#include <cuda_bf16.h>
#include <cstdint>

#define N_NODES 50000
#define E_EDGES 800000
#define S_SAMP  4
#define ADJ_STRIDE 128
#define GATHER_BLOCKS 6250    // N_NODES / 8
#define QT_TILE 128
#define QT_BLOCKS ((N_NODES + QT_TILE - 1) / QT_TILE)   // 391
#define ZB_BLOCKS QT_BLOCKS                             // 391 (128 nodes per CTA)
#define PART_ROWS (ZB_BLOCKS * 8)                       // 3128
#define BSTRIDE 72            // q_mma B row stride (bf16 elems)
#define BS2 40                // z_mma Weps row stride (bf16 elems), conflict-free

// ---------------- scratch (static device globals; no allocs) ----------------
__device__ unsigned int g_eps_pack[S_SAMP * N_NODES];  // [n][s] 32-feature bitmasks (self bits)
__device__ unsigned int g_epsb[(size_t)N_NODES * 32];  // [n][f] 4 sample-bits as u8 lanes
__device__ int   g_cnt[N_NODES];
__device__ int   g_adj[(size_t)N_NODES * ADJ_STRIDE];
__device__ unsigned int g_qb[(size_t)N_NODES * 64];    // q bf16x2 [n][64 col-pairs]
__device__ unsigned int g_acc2[(size_t)N_NODES * 64];  // aggregated q-sums, bf16x2
__device__ unsigned int g_cntp[(size_t)N_NODES * 32];  // neighbor eps counts, 4x u8 per u32
__device__ float g_part[(size_t)PART_ROWS * S_SAMP * 128];
__device__ float g_part2[64 * S_SAMP * 128];
__device__ float g_means[S_SAMP * 128];

// ---------------- helpers ----------------
__device__ __forceinline__ float2 bf2_to_f2(uint32_t v) {
    return make_float2(__uint_as_float(v << 16), __uint_as_float(v & 0xFFFF0000u));
}

// split fp32 pair -> (hi bf16x2, lo bf16x2)
__device__ __forceinline__ void cvt_split(float2 v, uint32_t& hi, uint32_t& lo) {
    __nv_bfloat162 h2 = __floats2bfloat162_rn(v.x, v.y);
    float fx = __bfloat162float(h2.x), fy = __bfloat162float(h2.y);
    __nv_bfloat162 l2 = __floats2bfloat162_rn(v.x - fx, v.y - fy);
    hi = *(uint32_t*)&h2;
    lo = *(uint32_t*)&l2;
}

__device__ __forceinline__ void mma16816(float* c, const uint32_t* a, uint32_t b0, uint32_t b1) {
    asm volatile("mma.sync.aligned.m16n8k16.row.col.f32.bf16.bf16.f32 "
                 "{%0,%1,%2,%3}, {%4,%5,%6,%7}, {%8,%9}, {%0,%1,%2,%3};"
                 : "+f"(c[0]), "+f"(c[1]), "+f"(c[2]), "+f"(c[3])
                 : "r"(a[0]), "r"(a[1]), "r"(a[2]), "r"(a[3]), "r"(b0), "r"(b1));
}

// ---------------- pack: eps bitmasks + byte-transposed layout + zero cnt ----------------
// warp per node; lane = feature f. Also emits per-sample bitmasks for z_mma self bits.
__global__ void __launch_bounds__(256) pack_kernel(const float* __restrict__ eps) {
    int lane = threadIdx.x & 31, w = threadIdx.x >> 5;
    int n = blockIdx.x * 8 + w;            // exact: 6250*8 == N_NODES
    if (n >= N_NODES) return;
    if (lane == 0) g_cnt[n] = 0;

    unsigned b = 0;
    unsigned m0, m1, m2, m3;
    {
        float v = eps[((size_t)0 * N_NODES + n) * 32 + lane];
        unsigned bit = (v > 0.5f) ? 1u : 0u;
        m0 = __ballot_sync(0xffffffffu, bit);
        b |= bit;
    }
    {
        float v = eps[((size_t)1 * N_NODES + n) * 32 + lane];
        unsigned bit = (v > 0.5f) ? 1u : 0u;
        m1 = __ballot_sync(0xffffffffu, bit);
        b |= bit << 8;
    }
    {
        float v = eps[((size_t)2 * N_NODES + n) * 32 + lane];
        unsigned bit = (v > 0.5f) ? 1u : 0u;
        m2 = __ballot_sync(0xffffffffu, bit);
        b |= bit << 16;
    }
    {
        float v = eps[((size_t)3 * N_NODES + n) * 32 + lane];
        unsigned bit = (v > 0.5f) ? 1u : 0u;
        m3 = __ballot_sync(0xffffffffu, bit);
        b |= bit << 24;
    }
    g_epsb[(size_t)n * 32 + lane] = b;
    if (lane == 0)
        *(uint4*)&g_eps_pack[n * 4] = make_uint4(m0, m1, m2, m3);
}

__global__ void fill_kernel(const int* __restrict__ src, const int* __restrict__ dst) {
    int e = blockIdx.x * blockDim.x + threadIdx.x;
    if (e < E_EDGES) {
        int d = dst[e];
        int slot = atomicAdd(&g_cnt[d], 1);
        if (slot < ADJ_STRIDE)
            g_adj[(size_t)d * ADJ_STRIDE + slot] = src[e];
    }
}

// ---------------- q = [X,h] @ W_shared via mma.sync split-bf16 ----------------
__global__ void __launch_bounds__(256) q_mma_kernel(const float* __restrict__ X,
                                                    const float* __restrict__ H,
                                                    const float* __restrict__ W) {
    __shared__ __nv_bfloat16 Bhi[128 * BSTRIDE];
    __shared__ __nv_bfloat16 Blo[128 * BSTRIDE];

    int tid = threadIdx.x, lane = tid & 31, wid = tid >> 5;
    int tg = lane & 3;
    int node0 = blockIdx.x * QT_TILE;
    int m0 = node0 + wid * 16 + (lane >> 2);
    bool v0 = m0 < N_NODES, v1 = (m0 + 8) < N_NODES;

    const float* rowX0 = X + (size_t)m0 * 96;
    const float* rowH0 = H + (size_t)m0 * 32;
    const float* rowX1 = rowX0 + 8 * 96;
    const float* rowH1 = rowH0 + 8 * 32;

    float C[16][4];
    #pragma unroll
    for (int t = 0; t < 16; t++)
        #pragma unroll
        for (int i = 0; i < 4; i++) C[t][i] = 0.f;

    int bn = lane >> 2;
    int bk = (lane & 3) * 2;

    for (int half = 0; half < 2; half++) {
        __syncthreads();
        for (int idx = tid; idx < 32 * 128; idx += 256) {
            int kp = idx >> 7, n = idx & 127;
            int k = half * 64 + kp * 2;
            int wr0 = (k < 96) ? k : (k + 32);
            int wr1 = (k + 1 < 96) ? (k + 1) : (k + 33);
            float2 v = make_float2(W[wr0 * 128 + n], W[wr1 * 128 + n]);
            uint32_t hi, lo;
            cvt_split(v, hi, lo);
            *(uint32_t*)&Bhi[n * BSTRIDE + kp * 2] = hi;
            *(uint32_t*)&Blo[n * BSTRIDE + kp * 2] = lo;
        }
        __syncthreads();

        #pragma unroll
        for (int ks = 0; ks < 4; ks++) {
            int k0 = half * 64 + ks * 16;
            uint32_t a_hi[4], a_lo[4];
            int kA = k0 + tg * 2;
            int kB = kA + 8;
            float2 z = make_float2(0.f, 0.f);
            float2 p0, p1, p2, p3;
            if (k0 < 96) {
                p0 = v0 ? *(const float2*)(rowX0 + kA) : z;
                p1 = v1 ? *(const float2*)(rowX1 + kA) : z;
                p2 = v0 ? *(const float2*)(rowX0 + kB) : z;
                p3 = v1 ? *(const float2*)(rowX1 + kB) : z;
            } else {
                p0 = v0 ? *(const float2*)(rowH0 + kA - 96) : z;
                p1 = v1 ? *(const float2*)(rowH1 + kA - 96) : z;
                p2 = v0 ? *(const float2*)(rowH0 + kB - 96) : z;
                p3 = v1 ? *(const float2*)(rowH1 + kB - 96) : z;
            }
            cvt_split(p0, a_hi[0], a_lo[0]);
            cvt_split(p1, a_hi[1], a_lo[1]);
            cvt_split(p2, a_hi[2], a_lo[2]);
            cvt_split(p3, a_hi[3], a_lo[3]);

            int klo = ks * 16 + bk;
            #pragma unroll
            for (int p = 0; p < 8; p++) {
                const __nv_bfloat16* hrow0 = &Bhi[(p * 16 + bn) * BSTRIDE + klo];
                const __nv_bfloat16* hrow1 = &Bhi[(p * 16 + 8 + bn) * BSTRIDE + klo];
                const __nv_bfloat16* lrow0 = &Blo[(p * 16 + bn) * BSTRIDE + klo];
                const __nv_bfloat16* lrow1 = &Blo[(p * 16 + 8 + bn) * BSTRIDE + klo];
                uint32_t bh0 = *(const uint32_t*)(hrow0);
                uint32_t bh1 = *(const uint32_t*)(hrow0 + 8);
                uint32_t bh2 = *(const uint32_t*)(hrow1);
                uint32_t bh3 = *(const uint32_t*)(hrow1 + 8);
                uint32_t bl0 = *(const uint32_t*)(lrow0);
                uint32_t bl1 = *(const uint32_t*)(lrow0 + 8);
                uint32_t bl2 = *(const uint32_t*)(lrow1);
                uint32_t bl3 = *(const uint32_t*)(lrow1 + 8);
                mma16816(C[2 * p],     a_hi, bh0, bh1);
                mma16816(C[2 * p],     a_hi, bl0, bl1);
                mma16816(C[2 * p],     a_lo, bh0, bh1);
                mma16816(C[2 * p + 1], a_hi, bh2, bh3);
                mma16816(C[2 * p + 1], a_hi, bl2, bl3);
                mma16816(C[2 * p + 1], a_lo, bh2, bh3);
            }
        }
    }

    #pragma unroll
    for (int t = 0; t < 16; t++) {
        int pairidx = t * 4 + tg;
        if (v0) {
            __nv_bfloat162 b2 = __floats2bfloat162_rn(C[t][0], C[t][1]);
            g_qb[(size_t)m0 * 64 + pairidx] = *(uint32_t*)&b2;
        }
        if (v1) {
            __nv_bfloat162 b2 = __floats2bfloat162_rn(C[t][2], C[t][3]);
            g_qb[(size_t)(m0 + 8) * 64 + pairidx] = *(uint32_t*)&b2;
        }
    }
}

// ---------------- gather: bf16 neighbor-sum + byte-packed eps counts ----------------
// warp = node; per edge: LDG.64 (q) + LDG.32 (epsb) + 2 HADD2 + 1 IADD.
__global__ void __launch_bounds__(256) gather_kernel(const float* __restrict__ gin_eps) {
    int lane = threadIdx.x & 31, wid = threadIdx.x >> 5;
    int n = blockIdx.x * 8 + wid;          // exact: 6250*8 == N_NODES
    float c0 = 1.f + *gin_eps;

    uint2 sp = *(const uint2*)&g_qb[(size_t)n * 64 + lane * 2];
    float2 s0 = bf2_to_f2(sp.x), s1 = bf2_to_f2(sp.y);
    __nv_bfloat162 acc0 = __floats2bfloat162_rn(c0 * s0.x, c0 * s0.y);
    __nv_bfloat162 acc1 = __floats2bfloat162_rn(c0 * s1.x, c0 * s1.y);

    unsigned cntp = 0;
    int deg = g_cnt[n];
    if (deg > ADJ_STRIDE) deg = ADJ_STRIDE;
    const int* adj = &g_adj[(size_t)n * ADJ_STRIDE];
    #pragma unroll 4
    for (int e = 0; e < deg; e++) {
        int j = adj[e];
        uint2 qp = *(const uint2*)&g_qb[(size_t)j * 64 + lane * 2];
        acc0 = __hadd2(acc0, *(__nv_bfloat162*)&qp.x);
        acc1 = __hadd2(acc1, *(__nv_bfloat162*)&qp.y);
        cntp += g_epsb[(size_t)j * 32 + lane];
    }

    *(uint2*)&g_acc2[(size_t)n * 64 + lane * 2] =
        make_uint2(*(uint32_t*)&acc0, *(uint32_t*)&acc1);
    g_cntp[(size_t)n * 32 + lane] = cntp;
}

// ---------------- z = acc + Coeff@Weps + bias, relu, row-fold -> g_part ----------------
__global__ void __launch_bounds__(256) z_mma_kernel(const float* __restrict__ W,
                                                    const float* __restrict__ bias,
                                                    const float* __restrict__ gin_eps) {
    __shared__ __nv_bfloat16 Wbh[128 * BS2];
    __shared__ __nv_bfloat16 Wbl[128 * BS2];

    int tid = threadIdx.x, lane = tid & 31, wid = tid >> 5;
    int tg = lane & 3, bn = lane >> 2;
    int node0 = blockIdx.x * 128;
    int m0 = node0 + wid * 16 + bn;
    bool v0 = m0 < N_NODES, v1 = (m0 + 8) < N_NODES;
    float c0 = 1.f + *gin_eps;
    int kAb = tg * 2;

    for (int idx = tid; idx < 128 * 32; idx += 256) {
        int col = idx >> 5, f = idx & 31;
        float w = W[(96 + f) * 128 + col];
        __nv_bfloat16 h = __float2bfloat16(w);
        Wbh[col * BS2 + f] = h;
        Wbl[col * BS2 + f] = __float2bfloat16(w - __bfloat162float(h));
    }

    uint2 cp0[4], cp1[4];
    #pragma unroll
    for (int o = 0; o < 4; o++) {
        cp0[o] = v0 ? *(const uint2*)&g_cntp[(size_t)m0 * 32 + o * 8 + kAb] : make_uint2(0u, 0u);
        cp1[o] = v1 ? *(const uint2*)&g_cntp[(size_t)(m0 + 8) * 32 + o * 8 + kAb] : make_uint2(0u, 0u);
    }
    uint4 sb0 = v0 ? *(const uint4*)&g_eps_pack[m0 * 4] : make_uint4(0u, 0u, 0u, 0u);
    uint4 sb1 = v1 ? *(const uint4*)&g_eps_pack[(m0 + 8) * 4] : make_uint4(0u, 0u, 0u, 0u);

    float accb0[16][2], accb1[16][2];
    #pragma unroll
    for (int t = 0; t < 16; t++) {
        int col = t * 8 + kAb;
        float bv0 = bias[col], bv1 = bias[col + 1];
        uint32_t a0 = v0 ? g_acc2[(size_t)m0 * 64 + (col >> 1)] : 0u;
        uint32_t a1 = v1 ? g_acc2[(size_t)(m0 + 8) * 64 + (col >> 1)] : 0u;
        float2 f0 = bf2_to_f2(a0), f1 = bf2_to_f2(a1);
        accb0[t][0] = f0.x + bv0; accb0[t][1] = f0.y + bv1;
        accb1[t][0] = f1.x + bv0; accb1[t][1] = f1.y + bv1;
    }
    __syncthreads();

    #pragma unroll 1
    for (int s = 0; s < 4; s++) {
        unsigned sw0 = (s == 0) ? sb0.x : (s == 1) ? sb0.y : (s == 2) ? sb0.z : sb0.w;
        unsigned sw1 = (s == 0) ? sb1.x : (s == 1) ? sb1.y : (s == 2) ? sb1.z : sb1.w;
        int sh = s * 8;

        float C[16][4];
        #pragma unroll
        for (int t = 0; t < 16; t++) { C[t][0] = C[t][1] = C[t][2] = C[t][3] = 0.f; }

        #pragma unroll
        for (int ks = 0; ks < 2; ks++) {
            uint32_t a_hi[4], a_lo[4];
            #pragma unroll
            for (int half = 0; half < 2; half++) {
                int o = ks * 2 + half;
                int fb = ks * 16 + half * 8 + kAb;
                {
                    float cf0 = (float)((cp0[o].x >> sh) & 0xFFu) + c0 * (float)((sw0 >> fb) & 1u);
                    float cf1 = (float)((cp0[o].y >> sh) & 0xFFu) + c0 * (float)((sw0 >> (fb + 1)) & 1u);
                    cvt_split(make_float2(cf0, cf1), a_hi[half * 2], a_lo[half * 2]);
                }
                {
                    float cf0 = (float)((cp1[o].x >> sh) & 0xFFu) + c0 * (float)((sw1 >> fb) & 1u);
                    float cf1 = (float)((cp1[o].y >> sh) & 0xFFu) + c0 * (float)((sw1 >> (fb + 1)) & 1u);
                    cvt_split(make_float2(cf0, cf1), a_hi[half * 2 + 1], a_lo[half * 2 + 1]);
                }
            }

            int klo = ks * 16 + kAb;
            #pragma unroll
            for (int p = 0; p < 8; p++) {
                const __nv_bfloat16* h0 = &Wbh[(p * 16 + bn) * BS2 + klo];
                const __nv_bfloat16* h1 = &Wbh[(p * 16 + 8 + bn) * BS2 + klo];
                const __nv_bfloat16* l0 = &Wbl[(p * 16 + bn) * BS2 + klo];
                const __nv_bfloat16* l1 = &Wbl[(p * 16 + 8 + bn) * BS2 + klo];
                uint32_t bh0 = *(const uint32_t*)h0, bh1 = *(const uint32_t*)(h0 + 8);
                uint32_t bh2 = *(const uint32_t*)h1, bh3 = *(const uint32_t*)(h1 + 8);
                uint32_t bl0 = *(const uint32_t*)l0, bl1 = *(const uint32_t*)(l0 + 8);
                uint32_t bl2 = *(const uint32_t*)l1, bl3 = *(const uint32_t*)(l1 + 8);
                mma16816(C[2 * p],     a_hi, bh0, bh1);
                mma16816(C[2 * p],     a_hi, bl0, bl1);
                mma16816(C[2 * p],     a_lo, bh0, bh1);
                mma16816(C[2 * p + 1], a_hi, bh2, bh3);
                mma16816(C[2 * p + 1], a_hi, bl2, bl3);
                mma16816(C[2 * p + 1], a_lo, bh2, bh3);
            }
        }

        #pragma unroll
        for (int t = 0; t < 16; t++) {
            float r0 = 0.f, r1 = 0.f;
            if (v0) {
                r0 += fmaxf(C[t][0] + accb0[t][0], 0.f);
                r1 += fmaxf(C[t][1] + accb0[t][1], 0.f);
            }
            if (v1) {
                r0 += fmaxf(C[t][2] + accb1[t][0], 0.f);
                r1 += fmaxf(C[t][3] + accb1[t][1], 0.f);
            }
            #pragma unroll
            for (int d = 4; d < 32; d <<= 1) {
                r0 += __shfl_xor_sync(0xffffffffu, r0, d);
                r1 += __shfl_xor_sync(0xffffffffu, r1, d);
            }
            if (lane < 4) {
                size_t row = (size_t)blockIdx.x * 8 + wid;
                *(float2*)&g_part[row * 512 + s * 128 + t * 8 + lane * 2] = make_float2(r0, r1);
            }
        }
    }
}

// ---------------- two-stage deterministic mean reduction ----------------
__global__ void reduce1_kernel() {
    int tid = threadIdx.x;
    int b = blockIdx.x;
    float v = 0.f;
    for (int i = b; i < PART_ROWS; i += 64) v += g_part[(size_t)i * 512 + tid];
    g_part2[b * 512 + tid] = v;
}
__global__ void reduce2_kernel() {
    int tid = threadIdx.x;
    float v = 0.f;
    #pragma unroll
    for (int i = 0; i < 64; i++) v += g_part2[i * 512 + tid];
    g_means[tid] = fmaxf(v * (1.f / (float)N_NODES), 0.f);
}

// ---------------- broadcast means + epsilon tail -> output ----------------
__global__ void bcast_kernel(float4* __restrict__ out,
                             const float4* __restrict__ eps,
                             long long out_size_f4) {
    const int MAIN_F4 = S_SAMP * N_NODES * 32;
    const int EPS_F4  = S_SAMP * N_NODES * 8;
    int idx = blockIdx.x * blockDim.x + threadIdx.x;
    if (idx < MAIN_F4) {
        if ((long long)idx < out_size_f4) {
            int s = idx / (N_NODES * 32);
            int c4 = idx & 31;
            out[idx] = ((const float4*)g_means)[s * 32 + c4];
        }
    } else {
        int k = idx - MAIN_F4;
        if (k < EPS_F4 && (long long)idx < out_size_f4) {
            out[idx] = eps[k];
        }
    }
}

// ---------------- launch ----------------
extern "C" void kernel_launch(void* const* d_in, const int* in_sizes, int n_in,
                              void* d_out, int out_size) {
    const float* X    = (const float*)d_in[0];
    const float* H    = (const float*)d_in[1];
    const float* eps  = (const float*)d_in[2];
    const float* W    = (const float*)d_in[3];
    const float* bias = (const float*)d_in[4];
    const float* geps = (const float*)d_in[5];
    const int*   src  = (const int*)d_in[6];
    const int*   dst  = (const int*)d_in[7];

    pack_kernel<<<GATHER_BLOCKS, 256>>>(eps);
    fill_kernel<<<(E_EDGES + 255) / 256, 256>>>(src, dst);
    q_mma_kernel<<<QT_BLOCKS, 256>>>(X, H, W);
    gather_kernel<<<GATHER_BLOCKS, 256>>>(geps);
    z_mma_kernel<<<ZB_BLOCKS, 256>>>(W, bias, geps);
    reduce1_kernel<<<64, 512>>>();
    reduce2_kernel<<<1, 512>>>();

    int total_f4 = S_SAMP * N_NODES * 32 + S_SAMP * N_NODES * 8;
    bcast_kernel<<<(total_f4 + 255) / 256, 256>>>((float4*)d_out,
                                                  (const float4*)eps,
                                                  (long long)out_size / 4);
}